// round 6
// baseline (speedup 1.0000x reference)
#include <cuda_runtime.h>

// ---------------- problem constants ----------------
#define SHIFT_  4
#define SCALE_  0.1767766952966369f   // 32^-0.5
#define TOK     262144                // B*H*W
#define C_      192
#define XS      196                   // padded row stride for s_x / s_o
#define ATTN_SMEM_BYTES 209944
#define MLP_SMEM_BYTES  164096

// ---------------- device scratch (no allocs allowed) ----------------
static __device__ float g_h[TOK * C_];          // h = shortcut + attn_out (input to MLP)
static __device__ float g_qkvt[192 * 576];      // qkv_w transposed [k][o]
static __device__ float g_projt[192 * 192];     // proj_w transposed [k][o]
static __device__ float g_fc1t[192 * 768];      // fc1_w transposed  [k][o]
static __device__ float g_fc2t[768 * 192];      // fc2_w transposed  [k][o]

// ---------------- weight transposes ----------------
__global__ void prep_kernel(const float* __restrict__ qkv_w,
                            const float* __restrict__ proj_w,
                            const float* __restrict__ fc1_w,
                            const float* __restrict__ fc2_w) {
    int idx = blockIdx.x * blockDim.x + threadIdx.x;
    int stride = gridDim.x * blockDim.x;
    for (int i = idx; i < 192 * 576; i += stride) {
        int k = i / 576, o = i - k * 576;
        g_qkvt[i] = qkv_w[o * 192 + k];
    }
    for (int i = idx; i < 192 * 192; i += stride) {
        int k = i / 192, o = i - k * 192;
        g_projt[i] = proj_w[o * 192 + k];
    }
    for (int i = idx; i < 192 * 768; i += stride) {
        int k = i / 768, o = i - k * 768;
        g_fc1t[i] = fc1_w[o * 192 + k];
    }
    for (int i = idx; i < 768 * 192; i += stride) {
        int k = i / 192, o = i - k * 192;
        g_fc2t[i] = fc2_w[o * 768 + k];
    }
}

// ---------------- fused window attention ----------------
// One CTA per window. 384 threads.
// smem layout (floats):
//   s_x   [64][196]  LN'd tokens, later reused as attention output s_o
//   s_q   [64][193]  (padded stride -> conflict-free per-lane scalar reads)
//   s_k   [64][192]
//   s_v   [64][192]
//   s_w   [8][192]   weight staging tile
//   s_rpb [1350]     relative-position bias table
//   s_lab [64] int   shift-mask region label per token
//   s_row [64] int   global token row for gather/scatter
__global__ __launch_bounds__(384, 1)
void attn_kernel(const float* __restrict__ x,
                 const float* __restrict__ n1g, const float* __restrict__ n1b,
                 const float* __restrict__ qkv_b,
                 const float* __restrict__ proj_b,
                 const float* __restrict__ rpb) {
    extern __shared__ float sm[];
    float* s_x   = sm;                      // 12544
    float* s_q   = s_x + 64 * XS;           // 12352
    float* s_k   = s_q + 64 * 193;          // 12288
    float* s_v   = s_k + 64 * 192;          // 12288
    float* s_w   = s_v + 64 * 192;          // 1536
    float* s_rpb = s_w + 1536;              // 1350
    int*   s_lab = (int*)(s_rpb + 1350);    // 64
    int*   s_row = s_lab + 64;              // 64

    const int tid  = threadIdx.x;
    const int w    = blockIdx.x;
    const int bimg = w >> 8;        // image index
    const int widx = w & 255;       // window within image
    const int wh   = widx >> 4, ww = widx & 15;

    // stage rpb table
    for (int i = tid; i < 1350; i += 384) s_rpb[i] = rpb[i];

    // -------- LN1 + shifted-window gather --------
    if (tid < 64) {
        int r = tid >> 3, c2 = tid & 7;
        int hs = wh * 8 + r, wsc = ww * 8 + c2;          // shifted-grid coords
        int h0 = (hs + SHIFT_) & 127;                    // original coords
        int w0 = (wsc + SHIFT_) & 127;
        int row = bimg * 16384 + h0 * 128 + w0;
        s_row[tid] = row;
        int hreg = hs < 120 ? 0 : (hs < 124 ? 1 : 2);
        int wreg = wsc < 120 ? 0 : (wsc < 124 ? 1 : 2);
        s_lab[tid] = hreg * 3 + wreg;

        const float* xr = x + (size_t)row * 192;
        float s = 0.f, ss = 0.f;
        #pragma unroll 8
        for (int k4 = 0; k4 < 192; k4 += 4) {
            float4 v = *(const float4*)(xr + k4);
            s  += v.x + v.y + v.z + v.w;
            ss += v.x * v.x + v.y * v.y + v.z * v.z + v.w * v.w;
        }
        float mu   = s * (1.f / 192.f);
        float var  = ss * (1.f / 192.f) - mu * mu;
        float rstd = rsqrtf(var + 1e-5f);
        for (int k = 0; k < 192; ++k)
            s_x[tid * XS + k] = (xr[k] - mu) * rstd * n1g[k] + n1b[k];
    }
    __syncthreads();

    // GEMM thread mapping: 16 n-groups x 24 o-groups, 4n x 8o tiles
    const int ng = tid / 24, og = tid % 24;
    const int n0 = ng * 4,   o0 = og * 8;
    // staging mapping: 8 kk x 48 o4
    const int skk = tid / 48, soq = tid % 48;

    // -------- Phase A: qkv projection (3 passes of N=192) --------
    for (int p = 0; p < 3; ++p) {
        float acc[4][8] = {};
        for (int kb = 0; kb < 192; kb += 8) {
            *(float4*)(s_w + skk * 192 + soq * 4) =
                *(const float4*)(g_qkvt + (kb + skk) * 576 + p * 192 + soq * 4);
            __syncthreads();
            #pragma unroll
            for (int kk = 0; kk < 8; ++kk) {
                float4 bL = *(float4*)(s_w + kk * 192 + o0);
                float4 bH = *(float4*)(s_w + kk * 192 + o0 + 4);
                #pragma unroll
                for (int i = 0; i < 4; ++i) {
                    float a = s_x[(n0 + i) * XS + kb + kk];
                    acc[i][0] += a * bL.x; acc[i][1] += a * bL.y;
                    acc[i][2] += a * bL.z; acc[i][3] += a * bL.w;
                    acc[i][4] += a * bH.x; acc[i][5] += a * bH.y;
                    acc[i][6] += a * bH.z; acc[i][7] += a * bH.w;
                }
            }
            __syncthreads();
        }
        #pragma unroll
        for (int i = 0; i < 4; ++i) {
            int n = n0 + i;
            #pragma unroll
            for (int j = 0; j < 8; ++j) {
                float v = acc[i][j] + qkv_b[p * 192 + o0 + j];
                if (p == 0)      s_q[n * 193 + o0 + j] = v * SCALE_;
                else if (p == 1) s_k[n * 192 + o0 + j] = v;
                else             s_v[n * 192 + o0 + j] = v;
            }
        }
    }
    __syncthreads();

    // -------- Phase B: attention, one thread per (head, query) --------
    {
        const int head = tid / 64;       // 0..5
        const int n    = tid & 63;
        const int hb   = head * 32;
        float qv[32];
        #pragma unroll
        for (int d = 0; d < 32; ++d) qv[d] = s_q[n * 193 + hb + d];

        float sc[64];
        const int i1 = n >> 3, j1 = n & 7;
        const int labn = s_lab[n];
        #pragma unroll
        for (int m = 0; m < 64; ++m) {
            const float* kr = s_k + m * 192 + hb;
            float s = 0.f;
            #pragma unroll
            for (int dq = 0; dq < 8; ++dq) {
                float4 k4 = *(const float4*)(kr + dq * 4);
                s += qv[dq * 4 + 0] * k4.x + qv[dq * 4 + 1] * k4.y
                   + qv[dq * 4 + 2] * k4.z + qv[dq * 4 + 3] * k4.w;
            }
            int i2 = m >> 3, j2 = m & 7;
            int ridx = (i1 - i2 + 7) * 15 + (j1 - j2 + 7);
            s += s_rpb[ridx * 6 + head];
            if (labn != s_lab[m]) s -= 100.f;
            sc[m] = s;
        }
        float mx = sc[0];
        #pragma unroll
        for (int m = 1; m < 64; ++m) mx = fmaxf(mx, sc[m]);
        float sum = 0.f;
        #pragma unroll
        for (int m = 0; m < 64; ++m) { sc[m] = expf(sc[m] - mx); sum += sc[m]; }
        float inv = 1.f / sum;

        float ov[32] = {};
        #pragma unroll
        for (int m = 0; m < 64; ++m) {
            float pm = sc[m];
            const float* vr = s_v + m * 192 + hb;
            #pragma unroll
            for (int dq = 0; dq < 8; ++dq) {
                float4 v4 = *(const float4*)(vr + dq * 4);
                ov[dq * 4 + 0] += pm * v4.x; ov[dq * 4 + 1] += pm * v4.y;
                ov[dq * 4 + 2] += pm * v4.z; ov[dq * 4 + 3] += pm * v4.w;
            }
        }
        #pragma unroll
        for (int d = 0; d < 32; ++d) s_x[n * XS + hb + d] = ov[d] * inv;  // s_x reused as s_o
    }
    __syncthreads();

    // -------- Phase D: output projection + residual + scatter-back --------
    {
        float acc[4][8] = {};
        for (int kb = 0; kb < 192; kb += 8) {
            *(float4*)(s_w + skk * 192 + soq * 4) =
                *(const float4*)(g_projt + (kb + skk) * 192 + soq * 4);
            __syncthreads();
            #pragma unroll
            for (int kk = 0; kk < 8; ++kk) {
                float4 bL = *(float4*)(s_w + kk * 192 + o0);
                float4 bH = *(float4*)(s_w + kk * 192 + o0 + 4);
                #pragma unroll
                for (int i = 0; i < 4; ++i) {
                    float a = s_x[(n0 + i) * XS + kb + kk];
                    acc[i][0] += a * bL.x; acc[i][1] += a * bL.y;
                    acc[i][2] += a * bL.z; acc[i][3] += a * bL.w;
                    acc[i][4] += a * bH.x; acc[i][5] += a * bH.y;
                    acc[i][6] += a * bH.z; acc[i][7] += a * bH.w;
                }
            }
            __syncthreads();
        }
        #pragma unroll
        for (int i = 0; i < 4; ++i) {
            int row = s_row[n0 + i];
            const float* xr = x  + (size_t)row * 192 + o0;
            float*       hr = g_h + (size_t)row * 192 + o0;
            #pragma unroll
            for (int q = 0; q < 2; ++q) {
                float4 xv = *(const float4*)(xr + q * 4);
                float4 pb = *(const float4*)(proj_b + o0 + q * 4);
                float4 rv;
                rv.x = acc[i][q * 4 + 0] + pb.x + xv.x;
                rv.y = acc[i][q * 4 + 1] + pb.y + xv.y;
                rv.z = acc[i][q * 4 + 2] + pb.z + xv.z;
                rv.w = acc[i][q * 4 + 3] + pb.w + xv.w;
                *(float4*)(hr + q * 4) = rv;
            }
        }
    }
}

// ---------------- fused MLP (LN2 -> fc1 -> GELU -> fc2 -> +residual) ----------------
// One CTA per 64 tokens. 512 threads. Hidden dim (768) streamed in chunks of 64.
#define TS 65
__global__ __launch_bounds__(512, 1)
void mlp_kernel(const float* __restrict__ n2g, const float* __restrict__ n2b,
                const float* __restrict__ fc1_b, const float* __restrict__ fc2_b,
                float* __restrict__ out) {
    extern __shared__ float sm[];
    float* s_ln = sm;               // 64*192 = 12288
    float* s_t  = s_ln + 12288;     // 64*65  = 4160  (GELU(fc1) chunk, padded)
    float* w1t  = s_t + 4160;       // 192*64 = 12288
    float* w2t  = w1t + 12288;      // 64*192 = 12288

    const int tid = threadIdx.x;
    const size_t tokBase = (size_t)blockIdx.x * 64;

    // LN2
    if (tid < 64) {
        const float* hr = g_h + (tokBase + tid) * 192;
        float s = 0.f, ss = 0.f;
        #pragma unroll 8
        for (int k4 = 0; k4 < 192; k4 += 4) {
            float4 v = *(const float4*)(hr + k4);
            s  += v.x + v.y + v.z + v.w;
            ss += v.x * v.x + v.y * v.y + v.z * v.z + v.w * v.w;
        }
        float mu   = s * (1.f / 192.f);
        float rstd = rsqrtf(ss * (1.f / 192.f) - mu * mu + 1e-5f);
        for (int k = 0; k < 192; ++k)
            s_ln[tid * 192 + k] = (hr[k] - mu) * rstd * n2g[k] + n2b[k];
    }
    __syncthreads();

    // fc2-output accumulators: (ngr 0..31, cg 0..15) -> 2n x 12c
    const int cg  = tid & 15, ngr = tid >> 4;
    const int n0b = ngr * 2,  c0  = cg * 12;
    float acc2[2][12] = {};
    // fc1 mapping: (ngf 0..31, og 0..15) -> 2n x 4o
    const int og  = tid & 15, ngf = tid >> 4;
    const int n0f = ngf * 2,  o0f = og * 4;

    for (int oc = 0; oc < 768; oc += 64) {
        // stage w1t [192][64]
        #pragma unroll
        for (int rr = 0; rr < 6; ++rr) {
            int idx = rr * 512 + tid;           // float4 index, 0..3071
            int kl = idx >> 4, o4 = (idx & 15) * 4;
            *(float4*)(w1t + kl * 64 + o4) =
                *(const float4*)(g_fc1t + kl * 768 + oc + o4);
        }
        __syncthreads();

        // fc1 chunk GEMM: t[64][64] = s_ln @ w1 + b, then GELU
        float a1[2][4] = {};
        #pragma unroll 4
        for (int k = 0; k < 192; ++k) {
            float4 bv = *(float4*)(w1t + k * 64 + o0f);
            #pragma unroll
            for (int i = 0; i < 2; ++i) {
                float a = s_ln[(n0f + i) * 192 + k];
                a1[i][0] += a * bv.x; a1[i][1] += a * bv.y;
                a1[i][2] += a * bv.z; a1[i][3] += a * bv.w;
            }
        }
        #pragma unroll
        for (int i = 0; i < 2; ++i)
            #pragma unroll
            for (int j = 0; j < 4; ++j) {
                float vv = a1[i][j] + fc1_b[oc + o0f + j];
                vv = 0.5f * vv * (1.f + erff(vv * 0.70710678118654752f));
                s_t[(n0f + i) * TS + o0f + j] = vv;
            }
        __syncthreads();

        // stage w2t [64][192]
        #pragma unroll
        for (int rr = 0; rr < 6; ++rr) {
            int idx = rr * 512 + tid;           // float4 index
            int kk = idx / 48, c4 = (idx % 48) * 4;
            *(float4*)(w2t + kk * 192 + c4) =
                *(const float4*)(g_fc2t + (oc + kk) * 192 + c4);
        }
        __syncthreads();

        // fc2 partial accumulation
        #pragma unroll 2
        for (int kk = 0; kk < 64; ++kk) {
            float4 b0v = *(float4*)(w2t + kk * 192 + c0);
            float4 b1v = *(float4*)(w2t + kk * 192 + c0 + 4);
            float4 b2v = *(float4*)(w2t + kk * 192 + c0 + 8);
            #pragma unroll
            for (int i = 0; i < 2; ++i) {
                float a = s_t[(n0b + i) * TS + kk];
                acc2[i][0]  += a * b0v.x; acc2[i][1]  += a * b0v.y;
                acc2[i][2]  += a * b0v.z; acc2[i][3]  += a * b0v.w;
                acc2[i][4]  += a * b1v.x; acc2[i][5]  += a * b1v.y;
                acc2[i][6]  += a * b1v.z; acc2[i][7]  += a * b1v.w;
                acc2[i][8]  += a * b2v.x; acc2[i][9]  += a * b2v.y;
                acc2[i][10] += a * b2v.z; acc2[i][11] += a * b2v.w;
            }
        }
        __syncthreads();
    }

    // epilogue: out = h + fc2 + bias
    #pragma unroll
    for (int i = 0; i < 2; ++i) {
        size_t row = tokBase + n0b + i;
        const float* hr = g_h + row * 192 + c0;
        float*       orow = out + row * 192 + c0;
        #pragma unroll
        for (int q = 0; q < 3; ++q) {
            float4 hv = *(const float4*)(hr + q * 4);
            float4 bv = *(const float4*)(fc2_b + c0 + q * 4);
            float4 rv;
            rv.x = acc2[i][q * 4 + 0] + bv.x + hv.x;
            rv.y = acc2[i][q * 4 + 1] + bv.y + hv.y;
            rv.z = acc2[i][q * 4 + 2] + bv.z + hv.z;
            rv.w = acc2[i][q * 4 + 3] + bv.w + hv.w;
            *(float4*)(orow + q * 4) = rv;
        }
    }
}

// ---------------- launch ----------------
extern "C" void kernel_launch(void* const* d_in, const int* in_sizes, int n_in,
                              void* d_out, int out_size) {
    (void)in_sizes; (void)n_in; (void)out_size;
    const float* x      = (const float*)d_in[0];
    const float* n1g    = (const float*)d_in[1];
    const float* n1b    = (const float*)d_in[2];
    const float* qkv_w  = (const float*)d_in[3];
    const float* qkv_b  = (const float*)d_in[4];
    const float* proj_w = (const float*)d_in[5];
    const float* proj_b = (const float*)d_in[6];
    const float* rpb    = (const float*)d_in[7];
    const float* n2g    = (const float*)d_in[8];
    const float* n2b    = (const float*)d_in[9];
    const float* fc1_w  = (const float*)d_in[10];
    const float* fc1_b  = (const float*)d_in[11];
    const float* fc2_w  = (const float*)d_in[12];
    const float* fc2_b  = (const float*)d_in[13];
    float* out = (float*)d_out;

    cudaFuncSetAttribute(attn_kernel, cudaFuncAttributeMaxDynamicSharedMemorySize,
                         ATTN_SMEM_BYTES);
    cudaFuncSetAttribute(mlp_kernel, cudaFuncAttributeMaxDynamicSharedMemorySize,
                         MLP_SMEM_BYTES);

    prep_kernel<<<432, 256>>>(qkv_w, proj_w, fc1_w, fc2_w);
    attn_kernel<<<4096, 384, ATTN_SMEM_BYTES>>>(x, n1g, n1b, qkv_b, proj_b, rpb);
    mlp_kernel<<<4096, 512, MLP_SMEM_BYTES>>>(n2g, n2b, fc1_b, fc2_b, out);
}

// round 8
// speedup vs baseline: 1.7555x; 1.7555x over previous
#include <cuda_runtime.h>
#include <cstdint>

// ---------------- problem constants ----------------
#define SHIFT_  4
#define SCALE_  0.1767766952966369f   // 32^-0.5
#define TOK     262144                // B*H*W
#define C_      192
#define XS      196                   // padded row stride for s_x / s_o
#define ATTN_SMEM_BYTES 209944

// MLP tensor-core tile strides (floats)
#define MAS   196   // s_a stride  (== 4 mod 32: conflict-free A-frag LDS)
#define MBS1  72    // W1 chunk stride (== 8 mod 32: conflict-free B-frag LDS)
#define MBS2  200   // W2 chunk stride (== 8 mod 32)
#define MTS   68    // GELU activation stride (== 4 mod 32)
#define MLP_SMEM_BYTES ((128*MAS + 13824 + 128*MTS) * 4)   // 190464

// ---------------- device scratch (no allocs allowed) ----------------
static __device__ float g_h[TOK * C_];          // h = shortcut + attn_out (input to MLP)
static __device__ float g_qkvt[192 * 576];      // qkv_w transposed [k][o]
static __device__ float g_projt[192 * 192];     // proj_w transposed [k][o]
static __device__ float g_fc1t[192 * 768];      // fc1_w transposed  [k][o], tf32-rounded
static __device__ float g_fc2t[768 * 192];      // fc2_w transposed  [k][o], tf32-rounded

// ---------------- helpers ----------------
__device__ __forceinline__ uint32_t f2tf32(float x) {
    uint32_t r;
    asm("cvt.rna.tf32.f32 %0, %1;" : "=r"(r) : "f"(x));
    return r;
}
__device__ __forceinline__ float f2tf32f(float x) {
    return __uint_as_float(f2tf32(x));
}
__device__ __forceinline__ void mma8(float* c,
                                     uint32_t a0, uint32_t a1, uint32_t a2, uint32_t a3,
                                     uint32_t b0, uint32_t b1) {
    asm volatile(
        "mma.sync.aligned.m16n8k8.row.col.f32.tf32.tf32.f32 "
        "{%0,%1,%2,%3}, {%4,%5,%6,%7}, {%8,%9}, {%0,%1,%2,%3};"
        : "+f"(c[0]), "+f"(c[1]), "+f"(c[2]), "+f"(c[3])
        : "r"(a0), "r"(a1), "r"(a2), "r"(a3), "r"(b0), "r"(b1));
}
__device__ __forceinline__ uint32_t U(float x) { return __float_as_uint(x); }

// ---------------- weight transposes ----------------
__global__ void prep_kernel(const float* __restrict__ qkv_w,
                            const float* __restrict__ proj_w,
                            const float* __restrict__ fc1_w,
                            const float* __restrict__ fc2_w) {
    int idx = blockIdx.x * blockDim.x + threadIdx.x;
    int stride = gridDim.x * blockDim.x;
    for (int i = idx; i < 192 * 576; i += stride) {
        int k = i / 576, o = i - k * 576;
        g_qkvt[i] = qkv_w[o * 192 + k];
    }
    for (int i = idx; i < 192 * 192; i += stride) {
        int k = i / 192, o = i - k * 192;
        g_projt[i] = proj_w[o * 192 + k];
    }
    for (int i = idx; i < 192 * 768; i += stride) {
        int k = i / 768, o = i - k * 768;
        g_fc1t[i] = f2tf32f(fc1_w[o * 192 + k]);
    }
    for (int i = idx; i < 768 * 192; i += stride) {
        int k = i / 192, o = i - k * 192;
        g_fc2t[i] = f2tf32f(fc2_w[o * 768 + k]);
    }
}

// ---------------- fused window attention (unchanged, proven) ----------------
__global__ __launch_bounds__(384, 1)
void attn_kernel(const float* __restrict__ x,
                 const float* __restrict__ n1g, const float* __restrict__ n1b,
                 const float* __restrict__ qkv_b,
                 const float* __restrict__ proj_b,
                 const float* __restrict__ rpb) {
    extern __shared__ float sm[];
    float* s_x   = sm;                      // 12544
    float* s_q   = s_x + 64 * XS;           // 12352
    float* s_k   = s_q + 64 * 193;          // 12288
    float* s_v   = s_k + 64 * 192;          // 12288
    float* s_w   = s_v + 64 * 192;          // 1536
    float* s_rpb = s_w + 1536;              // 1350
    int*   s_lab = (int*)(s_rpb + 1350);    // 64
    int*   s_row = s_lab + 64;              // 64

    const int tid  = threadIdx.x;
    const int w    = blockIdx.x;
    const int bimg = w >> 8;
    const int widx = w & 255;
    const int wh   = widx >> 4, ww = widx & 15;

    for (int i = tid; i < 1350; i += 384) s_rpb[i] = rpb[i];

    if (tid < 64) {
        int r = tid >> 3, c2 = tid & 7;
        int hs = wh * 8 + r, wsc = ww * 8 + c2;
        int h0 = (hs + SHIFT_) & 127;
        int w0 = (wsc + SHIFT_) & 127;
        int row = bimg * 16384 + h0 * 128 + w0;
        s_row[tid] = row;
        int hreg = hs < 120 ? 0 : (hs < 124 ? 1 : 2);
        int wreg = wsc < 120 ? 0 : (wsc < 124 ? 1 : 2);
        s_lab[tid] = hreg * 3 + wreg;

        const float* xr = x + (size_t)row * 192;
        float s = 0.f, ss = 0.f;
        #pragma unroll 8
        for (int k4 = 0; k4 < 192; k4 += 4) {
            float4 v = *(const float4*)(xr + k4);
            s  += v.x + v.y + v.z + v.w;
            ss += v.x * v.x + v.y * v.y + v.z * v.z + v.w * v.w;
        }
        float mu   = s * (1.f / 192.f);
        float var  = ss * (1.f / 192.f) - mu * mu;
        float rstd = rsqrtf(var + 1e-5f);
        for (int k = 0; k < 192; ++k)
            s_x[tid * XS + k] = (xr[k] - mu) * rstd * n1g[k] + n1b[k];
    }
    __syncthreads();

    const int ng = tid / 24, og = tid % 24;
    const int n0 = ng * 4,   o0 = og * 8;
    const int skk = tid / 48, soq = tid % 48;

    // -------- Phase A: qkv projection --------
    for (int p = 0; p < 3; ++p) {
        float acc[4][8] = {};
        for (int kb = 0; kb < 192; kb += 8) {
            *(float4*)(s_w + skk * 192 + soq * 4) =
                *(const float4*)(g_qkvt + (kb + skk) * 576 + p * 192 + soq * 4);
            __syncthreads();
            #pragma unroll
            for (int kk = 0; kk < 8; ++kk) {
                float4 bL = *(float4*)(s_w + kk * 192 + o0);
                float4 bH = *(float4*)(s_w + kk * 192 + o0 + 4);
                #pragma unroll
                for (int i = 0; i < 4; ++i) {
                    float a = s_x[(n0 + i) * XS + kb + kk];
                    acc[i][0] += a * bL.x; acc[i][1] += a * bL.y;
                    acc[i][2] += a * bL.z; acc[i][3] += a * bL.w;
                    acc[i][4] += a * bH.x; acc[i][5] += a * bH.y;
                    acc[i][6] += a * bH.z; acc[i][7] += a * bH.w;
                }
            }
            __syncthreads();
        }
        #pragma unroll
        for (int i = 0; i < 4; ++i) {
            int n = n0 + i;
            #pragma unroll
            for (int j = 0; j < 8; ++j) {
                float v = acc[i][j] + qkv_b[p * 192 + o0 + j];
                if (p == 0)      s_q[n * 193 + o0 + j] = v * SCALE_;
                else if (p == 1) s_k[n * 192 + o0 + j] = v;
                else             s_v[n * 192 + o0 + j] = v;
            }
        }
    }
    __syncthreads();

    // -------- Phase B: attention --------
    {
        const int head = tid / 64;
        const int n    = tid & 63;
        const int hb   = head * 32;
        float qv[32];
        #pragma unroll
        for (int d = 0; d < 32; ++d) qv[d] = s_q[n * 193 + hb + d];

        float sc[64];
        const int i1 = n >> 3, j1 = n & 7;
        const int labn = s_lab[n];
        #pragma unroll
        for (int m = 0; m < 64; ++m) {
            const float* kr = s_k + m * 192 + hb;
            float s = 0.f;
            #pragma unroll
            for (int dq = 0; dq < 8; ++dq) {
                float4 k4 = *(const float4*)(kr + dq * 4);
                s += qv[dq * 4 + 0] * k4.x + qv[dq * 4 + 1] * k4.y
                   + qv[dq * 4 + 2] * k4.z + qv[dq * 4 + 3] * k4.w;
            }
            int i2 = m >> 3, j2 = m & 7;
            int ridx = (i1 - i2 + 7) * 15 + (j1 - j2 + 7);
            s += s_rpb[ridx * 6 + head];
            if (labn != s_lab[m]) s -= 100.f;
            sc[m] = s;
        }
        float mx = sc[0];
        #pragma unroll
        for (int m = 1; m < 64; ++m) mx = fmaxf(mx, sc[m]);
        float sum = 0.f;
        #pragma unroll
        for (int m = 0; m < 64; ++m) { sc[m] = expf(sc[m] - mx); sum += sc[m]; }
        float inv = 1.f / sum;

        float ov[32] = {};
        #pragma unroll
        for (int m = 0; m < 64; ++m) {
            float pm = sc[m];
            const float* vr = s_v + m * 192 + hb;
            #pragma unroll
            for (int dq = 0; dq < 8; ++dq) {
                float4 v4 = *(const float4*)(vr + dq * 4);
                ov[dq * 4 + 0] += pm * v4.x; ov[dq * 4 + 1] += pm * v4.y;
                ov[dq * 4 + 2] += pm * v4.z; ov[dq * 4 + 3] += pm * v4.w;
            }
        }
        #pragma unroll
        for (int d = 0; d < 32; ++d) s_x[n * XS + hb + d] = ov[d] * inv;
    }
    __syncthreads();

    // -------- Phase D: output projection + residual + scatter --------
    {
        float acc[4][8] = {};
        for (int kb = 0; kb < 192; kb += 8) {
            *(float4*)(s_w + skk * 192 + soq * 4) =
                *(const float4*)(g_projt + (kb + skk) * 192 + soq * 4);
            __syncthreads();
            #pragma unroll
            for (int kk = 0; kk < 8; ++kk) {
                float4 bL = *(float4*)(s_w + kk * 192 + o0);
                float4 bH = *(float4*)(s_w + kk * 192 + o0 + 4);
                #pragma unroll
                for (int i = 0; i < 4; ++i) {
                    float a = s_x[(n0 + i) * XS + kb + kk];
                    acc[i][0] += a * bL.x; acc[i][1] += a * bL.y;
                    acc[i][2] += a * bL.z; acc[i][3] += a * bL.w;
                    acc[i][4] += a * bH.x; acc[i][5] += a * bH.y;
                    acc[i][6] += a * bH.z; acc[i][7] += a * bH.w;
                }
            }
            __syncthreads();
        }
        #pragma unroll
        for (int i = 0; i < 4; ++i) {
            int row = s_row[n0 + i];
            const float* xr = x  + (size_t)row * 192 + o0;
            float*       hr = g_h + (size_t)row * 192 + o0;
            #pragma unroll
            for (int q = 0; q < 2; ++q) {
                float4 xv = *(const float4*)(xr + q * 4);
                float4 pb = *(const float4*)(proj_b + o0 + q * 4);
                float4 rv;
                rv.x = acc[i][q * 4 + 0] + pb.x + xv.x;
                rv.y = acc[i][q * 4 + 1] + pb.y + xv.y;
                rv.z = acc[i][q * 4 + 2] + pb.z + xv.z;
                rv.w = acc[i][q * 4 + 3] + pb.w + xv.w;
                *(float4*)(hr + q * 4) = rv;
            }
        }
    }
}

// ---------------- MLP via tf32 mma.sync ----------------
// One CTA per 128 tokens (grid 2048). 512 threads = 16 warps in an 8m x 2n grid.
// Warp (wm, wn): rows wm*16..wm*16+15; fc1 cols wn*32..+31 per chunk; fc2 cols wn*96..+95.
// Hidden dim (768) streamed in 12 chunks of 64; fc2 accumulators persist in registers.
__global__ __launch_bounds__(512, 1)
void mlp_kernel(const float* __restrict__ n2g, const float* __restrict__ n2b,
                const float* __restrict__ fc1_b, const float* __restrict__ fc2_b,
                float* __restrict__ out) {
    extern __shared__ float sm[];
    float* s_a = sm;                   // 128 x MAS  (LN'd tokens, tf32-rounded)
    float* s_b = s_a + 128 * MAS;      // 13824 floats: W1 chunk [192][72] / W2 chunk [64][200]
    float* s_t = s_b + 13824;          // 128 x MTS  (GELU(fc1) chunk, tf32-rounded)

    const int tid  = threadIdx.x;
    const int lane = tid & 31, warp = tid >> 5;
    const int g = lane >> 2, t = lane & 3;     // mma groupID / threadID-in-group
    const int wm = warp >> 1, wn = warp & 1;
    const int m0 = wm * 16;
    const size_t tokBase = (size_t)blockIdx.x * 128;

    // LN2 -> s_a (tf32-rounded)
    if (tid < 128) {
        const float* hr = g_h + (tokBase + tid) * 192;
        float s = 0.f, ss = 0.f;
        #pragma unroll 8
        for (int k4 = 0; k4 < 192; k4 += 4) {
            float4 v = *(const float4*)(hr + k4);
            s  += v.x + v.y + v.z + v.w;
            ss += v.x * v.x + v.y * v.y + v.z * v.z + v.w * v.w;
        }
        float mu   = s * (1.f / 192.f);
        float rstd = rsqrtf(ss * (1.f / 192.f) - mu * mu + 1e-5f);
        float* ar = s_a + tid * MAS;
        for (int k = 0; k < 192; ++k)
            ar[k] = f2tf32f((hr[k] - mu) * rstd * n2g[k] + n2b[k]);
    }

    float c2[12][4] = {};

    for (int oc = 0; oc < 768; oc += 64) {
        __syncthreads();   // prev chunk's fc2 done reading s_t / s_b (and LN done on iter 0)

        // stage W1 chunk: [192 k][64 n] -> s_b stride MBS1
        #pragma unroll
        for (int r = 0; r < 6; ++r) {
            int idx = r * 512 + tid;            // float4 index, 0..3071
            int k = idx >> 4, n4 = (idx & 15) << 2;
            float4 v = *(const float4*)(g_fc1t + k * 768 + oc + n4);
            *(float4*)(s_b + k * MBS1 + n4) = v;
        }
        __syncthreads();

        // fc1 chunk: C1[128x64] = A[128x192] @ W1chunk
        float c1[4][4] = {};
        #pragma unroll 4
        for (int ks = 0; ks < 24; ++ks) {
            int k0 = ks * 8;
            uint32_t a0 = U(s_a[(m0 + g)     * MAS + k0 + t]);
            uint32_t a1 = U(s_a[(m0 + g + 8) * MAS + k0 + t]);
            uint32_t a2 = U(s_a[(m0 + g)     * MAS + k0 + t + 4]);
            uint32_t a3 = U(s_a[(m0 + g + 8) * MAS + k0 + t + 4]);
            #pragma unroll
            for (int nt = 0; nt < 4; ++nt) {
                int n0c = wn * 32 + nt * 8;
                uint32_t b0 = U(s_b[(k0 + t)     * MBS1 + n0c + g]);
                uint32_t b1 = U(s_b[(k0 + t + 4) * MBS1 + n0c + g]);
                mma8(c1[nt], a0, a1, a2, a3, b0, b1);
            }
        }

        // GELU + bias -> s_t (tf32-rounded)
        #pragma unroll
        for (int nt = 0; nt < 4; ++nt) {
            int ncol = wn * 32 + nt * 8 + 2 * t;
            float b0f = fc1_b[oc + ncol], b1f = fc1_b[oc + ncol + 1];
            float v0 = c1[nt][0] + b0f, v1 = c1[nt][1] + b1f;
            float v2 = c1[nt][2] + b0f, v3 = c1[nt][3] + b1f;
            v0 = 0.5f * v0 * (1.f + erff(v0 * 0.70710678118654752f));
            v1 = 0.5f * v1 * (1.f + erff(v1 * 0.70710678118654752f));
            v2 = 0.5f * v2 * (1.f + erff(v2 * 0.70710678118654752f));
            v3 = 0.5f * v3 * (1.f + erff(v3 * 0.70710678118654752f));
            float2 lo = make_float2(f2tf32f(v0), f2tf32f(v1));
            float2 hi = make_float2(f2tf32f(v2), f2tf32f(v3));
            *(float2*)(s_t + (m0 + g)     * MTS + ncol) = lo;
            *(float2*)(s_t + (m0 + g + 8) * MTS + ncol) = hi;
        }
        __syncthreads();   // s_t visible; s_b (W1) reads complete

        // stage W2 chunk: [64 k][192 n] -> s_b stride MBS2
        #pragma unroll
        for (int r = 0; r < 6; ++r) {
            int idx = r * 512 + tid;            // float4 index, 0..3071
            int kk = idx / 48, c4 = (idx % 48) << 2;
            float4 v = *(const float4*)(g_fc2t + (oc + kk) * 192 + c4);
            *(float4*)(s_b + kk * MBS2 + c4) = v;
        }
        __syncthreads();

        // fc2 partial: C2[128x192] += T[128x64] @ W2chunk
        #pragma unroll
        for (int ks = 0; ks < 8; ++ks) {
            int k0 = ks * 8;
            uint32_t a0 = U(s_t[(m0 + g)     * MTS + k0 + t]);
            uint32_t a1 = U(s_t[(m0 + g + 8) * MTS + k0 + t]);
            uint32_t a2 = U(s_t[(m0 + g)     * MTS + k0 + t + 4]);
            uint32_t a3 = U(s_t[(m0 + g + 8) * MTS + k0 + t + 4]);
            #pragma unroll
            for (int nt = 0; nt < 12; ++nt) {
                int n0c = wn * 96 + nt * 8;
                uint32_t b0 = U(s_b[(k0 + t)     * MBS2 + n0c + g]);
                uint32_t b1 = U(s_b[(k0 + t + 4) * MBS2 + n0c + g]);
                mma8(c2[nt], a0, a1, a2, a3, b0, b1);
            }
        }
    }

    // epilogue: out = h + fc2 + bias
    #pragma unroll
    for (int nt = 0; nt < 12; ++nt) {
        int col = wn * 96 + nt * 8 + 2 * t;
        float2 bv = *(const float2*)(fc2_b + col);
        size_t r0 = tokBase + m0 + g;
        size_t r1 = r0 + 8;
        float2 h0 = *(const float2*)(g_h + r0 * 192 + col);
        float2 h1 = *(const float2*)(g_h + r1 * 192 + col);
        float2 o0 = make_float2(c2[nt][0] + bv.x + h0.x, c2[nt][1] + bv.y + h0.y);
        float2 o1 = make_float2(c2[nt][2] + bv.x + h1.x, c2[nt][3] + bv.y + h1.y);
        *(float2*)(out + r0 * 192 + col) = o0;
        *(float2*)(out + r1 * 192 + col) = o1;
    }
}

// ---------------- launch ----------------
extern "C" void kernel_launch(void* const* d_in, const int* in_sizes, int n_in,
                              void* d_out, int out_size) {
    (void)in_sizes; (void)n_in; (void)out_size;
    const float* x      = (const float*)d_in[0];
    const float* n1g    = (const float*)d_in[1];
    const float* n1b    = (const float*)d_in[2];
    const float* qkv_w  = (const float*)d_in[3];
    const float* qkv_b  = (const float*)d_in[4];
    const float* proj_w = (const float*)d_in[5];
    const float* proj_b = (const float*)d_in[6];
    const float* rpb    = (const float*)d_in[7];
    const float* n2g    = (const float*)d_in[8];
    const float* n2b    = (const float*)d_in[9];
    const float* fc1_w  = (const float*)d_in[10];
    const float* fc1_b  = (const float*)d_in[11];
    const float* fc2_w  = (const float*)d_in[12];
    const float* fc2_b  = (const float*)d_in[13];
    float* out = (float*)d_out;

    cudaFuncSetAttribute(attn_kernel, cudaFuncAttributeMaxDynamicSharedMemorySize,
                         ATTN_SMEM_BYTES);
    cudaFuncSetAttribute(mlp_kernel, cudaFuncAttributeMaxDynamicSharedMemorySize,
                         MLP_SMEM_BYTES);

    prep_kernel<<<432, 256>>>(qkv_w, proj_w, fc1_w, fc2_w);
    attn_kernel<<<4096, 384, ATTN_SMEM_BYTES>>>(x, n1g, n1b, qkv_b, proj_b, rpb);
    mlp_kernel<<<2048, 512, MLP_SMEM_BYTES>>>(n2g, n2b, fc1_b, fc2_b, out);
}

// round 10
// speedup vs baseline: 2.9903x; 1.7034x over previous
#include <cuda_runtime.h>
#include <cstdint>

// ---------------- problem constants ----------------
#define SHIFT_  4
#define SCALE_  0.1767766952966369f   // 32^-0.5
#define TOK     262144                // B*H*W
#define C_      192
#define XS      196                   // s_x stride (==4 mod 32: conflict-free A-frag LDS)
#define QS      194                   // s_q stride (even -> aligned float2 stores)
#define WS_     200                   // weight staging stride (==8 mod 32: conflict-free B-frag)
#define ATTN_SMEM_BYTES 223768

// MLP tensor-core tile strides (floats)
#define MAS   196
#define MBS1  72
#define MBS2  200
#define MTS   68
#define MLP_SMEM_BYTES ((128*MAS + 13824 + 128*MTS) * 4)   // 190464

// ---------------- device scratch (no allocs allowed) ----------------
static __device__ float g_h[TOK * C_];          // h = shortcut + attn_out
static __device__ float g_qkvt[192 * 576];      // qkv_w^T [k][o], tf32-rounded
static __device__ float g_projt[192 * 192];     // proj_w^T [k][o], tf32-rounded
static __device__ float g_fc1t[192 * 768];      // fc1_w^T  [k][o], tf32-rounded
static __device__ float g_fc2t[768 * 192];      // fc2_w^T  [k][o], tf32-rounded

// ---------------- helpers ----------------
__device__ __forceinline__ uint32_t f2tf32(float x) {
    uint32_t r;
    asm("cvt.rna.tf32.f32 %0, %1;" : "=r"(r) : "f"(x));
    return r;
}
__device__ __forceinline__ float f2tf32f(float x) {
    return __uint_as_float(f2tf32(x));
}
__device__ __forceinline__ void mma8(float* c,
                                     uint32_t a0, uint32_t a1, uint32_t a2, uint32_t a3,
                                     uint32_t b0, uint32_t b1) {
    asm volatile(
        "mma.sync.aligned.m16n8k8.row.col.f32.tf32.tf32.f32 "
        "{%0,%1,%2,%3}, {%4,%5,%6,%7}, {%8,%9}, {%0,%1,%2,%3};"
        : "+f"(c[0]), "+f"(c[1]), "+f"(c[2]), "+f"(c[3])
        : "r"(a0), "r"(a1), "r"(a2), "r"(a3), "r"(b0), "r"(b1));
}
__device__ __forceinline__ uint32_t U(float x) { return __float_as_uint(x); }

// ---------------- weight transposes (+ tf32 rounding) ----------------
__global__ void prep_kernel(const float* __restrict__ qkv_w,
                            const float* __restrict__ proj_w,
                            const float* __restrict__ fc1_w,
                            const float* __restrict__ fc2_w) {
    int idx = blockIdx.x * blockDim.x + threadIdx.x;
    int stride = gridDim.x * blockDim.x;
    for (int i = idx; i < 192 * 576; i += stride) {
        int k = i / 576, o = i - k * 576;
        g_qkvt[i] = f2tf32f(qkv_w[o * 192 + k]);
    }
    for (int i = idx; i < 192 * 192; i += stride) {
        int k = i / 192, o = i - k * 192;
        g_projt[i] = f2tf32f(proj_w[o * 192 + k]);
    }
    for (int i = idx; i < 192 * 768; i += stride) {
        int k = i / 768, o = i - k * 768;
        g_fc1t[i] = f2tf32f(fc1_w[o * 192 + k]);
    }
    for (int i = idx; i < 768 * 192; i += stride) {
        int k = i / 192, o = i - k * 192;
        g_fc2t[i] = f2tf32f(fc2_w[o * 768 + k]);
    }
}

// ---------------- fused window attention (tf32 mma GEMMs) ----------------
// One CTA per window (64 tokens). 384 threads = 12 warps in a 4m x 3n grid.
__global__ __launch_bounds__(384, 1)
void attn_kernel(const float* __restrict__ x,
                 const float* __restrict__ n1g, const float* __restrict__ n1b,
                 const float* __restrict__ qkv_b,
                 const float* __restrict__ proj_b,
                 const float* __restrict__ rpb) {
    extern __shared__ float sm[];
    float* s_x   = sm;                      // 64*196 = 12544
    float* s_q   = s_x + 64 * XS;           // 64*194 = 12416
    float* s_k   = s_q + 64 * QS;           // 64*192 = 12288
    float* s_v   = s_k + 64 * 192;          // 12288
    float* s_w   = s_v + 64 * 192;          // 24*200 = 4800
    float* s_rpb = s_w + 24 * WS_;          // 1350
    float* s_mu  = s_rpb + 1350;            // 64
    float* s_rs  = s_mu + 64;               // 64
    int*   s_lab = (int*)(s_rs + 64);       // 64
    int*   s_row = s_lab + 64;              // 64

    const int tid  = threadIdx.x;
    const int w    = blockIdx.x;
    const int bimg = w >> 8;
    const int widx = w & 255;
    const int wh   = widx >> 4, ww = widx & 15;

    for (int i = tid; i < 1350; i += 384) s_rpb[i] = rpb[i];

    // -------- LN1 stats + shifted-window metadata (64 threads) --------
    if (tid < 64) {
        int r = tid >> 3, c2 = tid & 7;
        int hs = wh * 8 + r, wsc = ww * 8 + c2;
        int h0 = (hs + SHIFT_) & 127;
        int w0 = (wsc + SHIFT_) & 127;
        int row = bimg * 16384 + h0 * 128 + w0;
        s_row[tid] = row;
        int hreg = hs < 120 ? 0 : (hs < 124 ? 1 : 2);
        int wreg = wsc < 120 ? 0 : (wsc < 124 ? 1 : 2);
        s_lab[tid] = hreg * 3 + wreg;

        const float* xr = x + (size_t)row * 192;
        float s = 0.f, ss = 0.f;
        #pragma unroll 8
        for (int k4 = 0; k4 < 192; k4 += 4) {
            float4 v = *(const float4*)(xr + k4);
            s  += v.x + v.y + v.z + v.w;
            ss += v.x * v.x + v.y * v.y + v.z * v.z + v.w * v.w;
        }
        float mu = s * (1.f / 192.f);
        s_mu[tid] = mu;
        s_rs[tid] = rsqrtf(ss * (1.f / 192.f) - mu * mu + 1e-5f);
    }
    __syncthreads();

    // -------- LN1 normalize, distributed over all 384 threads --------
    // each thread: 32 elements (64*192/384), vectorized float4 (8 per thread)
    {
        #pragma unroll
        for (int j = 0; j < 8; ++j) {
            int e4 = tid + j * 384;            // float4 index, 0..3071
            int row = e4 / 48, c4 = (e4 % 48) * 4;
            float mu = s_mu[row], rs = s_rs[row];
            float4 v = *(const float4*)(x + (size_t)s_row[row] * 192 + c4);
            float4 gv = *(const float4*)(n1g + c4);
            float4 bv = *(const float4*)(n1b + c4);
            float4 o;
            o.x = f2tf32f((v.x - mu) * rs * gv.x + bv.x);
            o.y = f2tf32f((v.y - mu) * rs * gv.y + bv.y);
            o.z = f2tf32f((v.z - mu) * rs * gv.z + bv.z);
            o.w = f2tf32f((v.w - mu) * rs * gv.w + bv.w);
            *(float4*)(s_x + row * XS + c4) = o;
        }
    }

    const int lane = tid & 31, warp = tid >> 5;
    const int g = lane >> 2, t = lane & 3;
    const int wm = warp >> 2;          // 0..2  (n-group: 3 groups of 64 cols)
    const int wq = warp & 3;           // 0..3  (m-group)
    // NOTE: map so warp = wq*? -- use: m-group = warp & 3, n-group = warp >> 2
    const int m0  = (warp & 3) * 16;
    const int n0c = (warp >> 2) * 64;
    (void)wm; (void)wq;

    // -------- Phase A: qkv projection via mma (3 passes of N=192) --------
    #pragma unroll 1
    for (int p = 0; p < 3; ++p) {
        float c1[8][4] = {};
        #pragma unroll 1
        for (int kb = 0; kb < 192; kb += 24) {
            __syncthreads();   // prev chunk mma done / LN done (first iter)
            // stage 24 k-rows x 192 cols of qkv_w^T
            #pragma unroll
            for (int r = 0; r < 3; ++r) {
                int idx = r * 384 + tid;        // float4 idx, 0..1151
                int kl = idx / 48, c4 = (idx % 48) * 4;
                *(float4*)(s_w + kl * WS_ + c4) =
                    *(const float4*)(g_qkvt + (kb + kl) * 576 + p * 192 + c4);
            }
            __syncthreads();
            #pragma unroll
            for (int ks = 0; ks < 3; ++ks) {
                int kg = kb + ks * 8;           // global k for A
                int kl = ks * 8;                // local k for B
                uint32_t a0 = U(s_x[(m0 + g)     * XS + kg + t]);
                uint32_t a1 = U(s_x[(m0 + g + 8) * XS + kg + t]);
                uint32_t a2 = U(s_x[(m0 + g)     * XS + kg + t + 4]);
                uint32_t a3 = U(s_x[(m0 + g + 8) * XS + kg + t + 4]);
                #pragma unroll
                for (int nt = 0; nt < 8; ++nt) {
                    uint32_t b0 = U(s_w[(kl + t)     * WS_ + n0c + nt * 8 + g]);
                    uint32_t b1 = U(s_w[(kl + t + 4) * WS_ + n0c + nt * 8 + g]);
                    mma8(c1[nt], a0, a1, a2, a3, b0, b1);
                }
            }
        }
        // store q/k/v
        #pragma unroll
        for (int nt = 0; nt < 8; ++nt) {
            int col = n0c + nt * 8 + 2 * t;
            float2 bv = *(const float2*)(qkv_b + p * 192 + col);
            int r0 = m0 + g, r1 = m0 + g + 8;
            if (p == 0) {
                float2 v0 = make_float2((c1[nt][0] + bv.x) * SCALE_,
                                        (c1[nt][1] + bv.y) * SCALE_);
                float2 v1 = make_float2((c1[nt][2] + bv.x) * SCALE_,
                                        (c1[nt][3] + bv.y) * SCALE_);
                *(float2*)(s_q + r0 * QS + col) = v0;
                *(float2*)(s_q + r1 * QS + col) = v1;
            } else {
                float* dst = (p == 1) ? s_k : s_v;
                float2 v0 = make_float2(c1[nt][0] + bv.x, c1[nt][1] + bv.y);
                float2 v1 = make_float2(c1[nt][2] + bv.x, c1[nt][3] + bv.y);
                *(float2*)(dst + r0 * 192 + col) = v0;
                *(float2*)(dst + r1 * 192 + col) = v1;
            }
        }
    }
    __syncthreads();

    // -------- Phase B: attention (SIMT, one thread per head x query) --------
    {
        const int head = tid / 64;
        const int n    = tid & 63;
        const int hb   = head * 32;
        float qv[32];
        #pragma unroll
        for (int d = 0; d < 32; ++d) qv[d] = s_q[n * QS + hb + d];

        float sc[64];
        const int i1 = n >> 3, j1 = n & 7;
        const int labn = s_lab[n];
        #pragma unroll
        for (int m = 0; m < 64; ++m) {
            const float* kr = s_k + m * 192 + hb;
            float s = 0.f;
            #pragma unroll
            for (int dq = 0; dq < 8; ++dq) {
                float4 k4 = *(const float4*)(kr + dq * 4);
                s += qv[dq * 4 + 0] * k4.x + qv[dq * 4 + 1] * k4.y
                   + qv[dq * 4 + 2] * k4.z + qv[dq * 4 + 3] * k4.w;
            }
            int i2 = m >> 3, j2 = m & 7;
            int ridx = (i1 - i2 + 7) * 15 + (j1 - j2 + 7);
            s += s_rpb[ridx * 6 + head];
            if (labn != s_lab[m]) s -= 100.f;
            sc[m] = s;
        }
        float mx = sc[0];
        #pragma unroll
        for (int m = 1; m < 64; ++m) mx = fmaxf(mx, sc[m]);
        float sum = 0.f;
        #pragma unroll
        for (int m = 0; m < 64; ++m) { sc[m] = expf(sc[m] - mx); sum += sc[m]; }
        float inv = 1.f / sum;

        float ov[32] = {};
        #pragma unroll
        for (int m = 0; m < 64; ++m) {
            float pm = sc[m];
            const float* vr = s_v + m * 192 + hb;
            #pragma unroll
            for (int dq = 0; dq < 8; ++dq) {
                float4 v4 = *(const float4*)(vr + dq * 4);
                ov[dq * 4 + 0] += pm * v4.x; ov[dq * 4 + 1] += pm * v4.y;
                ov[dq * 4 + 2] += pm * v4.z; ov[dq * 4 + 3] += pm * v4.w;
            }
        }
        #pragma unroll
        for (int d = 0; d < 32; ++d)
            s_x[n * XS + hb + d] = f2tf32f(ov[d] * inv);   // tf32 for proj mma
    }

    // -------- Phase D: output projection via mma + residual + scatter --------
    {
        float c1[8][4] = {};
        #pragma unroll 1
        for (int kb = 0; kb < 192; kb += 24) {
            __syncthreads();
            #pragma unroll
            for (int r = 0; r < 3; ++r) {
                int idx = r * 384 + tid;
                int kl = idx / 48, c4 = (idx % 48) * 4;
                *(float4*)(s_w + kl * WS_ + c4) =
                    *(const float4*)(g_projt + (kb + kl) * 192 + c4);
            }
            __syncthreads();
            #pragma unroll
            for (int ks = 0; ks < 3; ++ks) {
                int kg = kb + ks * 8;
                int kl = ks * 8;
                uint32_t a0 = U(s_x[(m0 + g)     * XS + kg + t]);
                uint32_t a1 = U(s_x[(m0 + g + 8) * XS + kg + t]);
                uint32_t a2 = U(s_x[(m0 + g)     * XS + kg + t + 4]);
                uint32_t a3 = U(s_x[(m0 + g + 8) * XS + kg + t + 4]);
                #pragma unroll
                for (int nt = 0; nt < 8; ++nt) {
                    uint32_t b0 = U(s_w[(kl + t)     * WS_ + n0c + nt * 8 + g]);
                    uint32_t b1 = U(s_w[(kl + t + 4) * WS_ + n0c + nt * 8 + g]);
                    mma8(c1[nt], a0, a1, a2, a3, b0, b1);
                }
            }
        }
        // residual + scatter to g_h
        int r0 = m0 + g, r1 = m0 + g + 8;
        size_t row0 = (size_t)s_row[r0], row1 = (size_t)s_row[r1];
        #pragma unroll
        for (int nt = 0; nt < 8; ++nt) {
            int col = n0c + nt * 8 + 2 * t;
            float2 pb = *(const float2*)(proj_b + col);
            float2 x0 = *(const float2*)(x + row0 * 192 + col);
            float2 x1 = *(const float2*)(x + row1 * 192 + col);
            float2 o0 = make_float2(c1[nt][0] + pb.x + x0.x,
                                    c1[nt][1] + pb.y + x0.y);
            float2 o1 = make_float2(c1[nt][2] + pb.x + x1.x,
                                    c1[nt][3] + pb.y + x1.y);
            *(float2*)(g_h + row0 * 192 + col) = o0;
            *(float2*)(g_h + row1 * 192 + col) = o1;
        }
    }
}

// ---------------- MLP via tf32 mma.sync (unchanged from R7) ----------------
__global__ __launch_bounds__(512, 1)
void mlp_kernel(const float* __restrict__ n2g, const float* __restrict__ n2b,
                const float* __restrict__ fc1_b, const float* __restrict__ fc2_b,
                float* __restrict__ out) {
    extern __shared__ float sm[];
    float* s_a = sm;
    float* s_b = s_a + 128 * MAS;
    float* s_t = s_b + 13824;

    const int tid  = threadIdx.x;
    const int lane = tid & 31, warp = tid >> 5;
    const int g = lane >> 2, t = lane & 3;
    const int wm = warp >> 1, wn = warp & 1;
    const int m0 = wm * 16;
    const size_t tokBase = (size_t)blockIdx.x * 128;

    if (tid < 128) {
        const float* hr = g_h + (tokBase + tid) * 192;
        float s = 0.f, ss = 0.f;
        #pragma unroll 8
        for (int k4 = 0; k4 < 192; k4 += 4) {
            float4 v = *(const float4*)(hr + k4);
            s  += v.x + v.y + v.z + v.w;
            ss += v.x * v.x + v.y * v.y + v.z * v.z + v.w * v.w;
        }
        float mu   = s * (1.f / 192.f);
        float rstd = rsqrtf(ss * (1.f / 192.f) - mu * mu + 1e-5f);
        float* ar = s_a + tid * MAS;
        for (int k = 0; k < 192; ++k)
            ar[k] = f2tf32f((hr[k] - mu) * rstd * n2g[k] + n2b[k]);
    }

    float c2[12][4] = {};

    for (int oc = 0; oc < 768; oc += 64) {
        __syncthreads();

        #pragma unroll
        for (int r = 0; r < 6; ++r) {
            int idx = r * 512 + tid;
            int k = idx >> 4, n4 = (idx & 15) << 2;
            float4 v = *(const float4*)(g_fc1t + k * 768 + oc + n4);
            *(float4*)(s_b + k * MBS1 + n4) = v;
        }
        __syncthreads();

        float c1[4][4] = {};
        #pragma unroll 4
        for (int ks = 0; ks < 24; ++ks) {
            int k0 = ks * 8;
            uint32_t a0 = U(s_a[(m0 + g)     * MAS + k0 + t]);
            uint32_t a1 = U(s_a[(m0 + g + 8) * MAS + k0 + t]);
            uint32_t a2 = U(s_a[(m0 + g)     * MAS + k0 + t + 4]);
            uint32_t a3 = U(s_a[(m0 + g + 8) * MAS + k0 + t + 4]);
            #pragma unroll
            for (int nt = 0; nt < 4; ++nt) {
                int n0c = wn * 32 + nt * 8;
                uint32_t b0 = U(s_b[(k0 + t)     * MBS1 + n0c + g]);
                uint32_t b1 = U(s_b[(k0 + t + 4) * MBS1 + n0c + g]);
                mma8(c1[nt], a0, a1, a2, a3, b0, b1);
            }
        }

        #pragma unroll
        for (int nt = 0; nt < 4; ++nt) {
            int ncol = wn * 32 + nt * 8 + 2 * t;
            float b0f = fc1_b[oc + ncol], b1f = fc1_b[oc + ncol + 1];
            float v0 = c1[nt][0] + b0f, v1 = c1[nt][1] + b1f;
            float v2 = c1[nt][2] + b0f, v3 = c1[nt][3] + b1f;
            v0 = 0.5f * v0 * (1.f + erff(v0 * 0.70710678118654752f));
            v1 = 0.5f * v1 * (1.f + erff(v1 * 0.70710678118654752f));
            v2 = 0.5f * v2 * (1.f + erff(v2 * 0.70710678118654752f));
            v3 = 0.5f * v3 * (1.f + erff(v3 * 0.70710678118654752f));
            float2 lo = make_float2(f2tf32f(v0), f2tf32f(v1));
            float2 hi = make_float2(f2tf32f(v2), f2tf32f(v3));
            *(float2*)(s_t + (m0 + g)     * MTS + ncol) = lo;
            *(float2*)(s_t + (m0 + g + 8) * MTS + ncol) = hi;
        }
        __syncthreads();

        #pragma unroll
        for (int r = 0; r < 6; ++r) {
            int idx = r * 512 + tid;
            int kk = idx / 48, c4 = (idx % 48) << 2;
            float4 v = *(const float4*)(g_fc2t + (oc + kk) * 192 + c4);
            *(float4*)(s_b + kk * MBS2 + c4) = v;
        }
        __syncthreads();

        #pragma unroll
        for (int ks = 0; ks < 8; ++ks) {
            int k0 = ks * 8;
            uint32_t a0 = U(s_t[(m0 + g)     * MTS + k0 + t]);
            uint32_t a1 = U(s_t[(m0 + g + 8) * MTS + k0 + t]);
            uint32_t a2 = U(s_t[(m0 + g)     * MTS + k0 + t + 4]);
            uint32_t a3 = U(s_t[(m0 + g + 8) * MTS + k0 + t + 4]);
            #pragma unroll
            for (int nt = 0; nt < 12; ++nt) {
                int n0c = wn * 96 + nt * 8;
                uint32_t b0 = U(s_b[(k0 + t)     * MBS2 + n0c + g]);
                uint32_t b1 = U(s_b[(k0 + t + 4) * MBS2 + n0c + g]);
                mma8(c2[nt], a0, a1, a2, a3, b0, b1);
            }
        }
    }

    #pragma unroll
    for (int nt = 0; nt < 12; ++nt) {
        int col = wn * 96 + nt * 8 + 2 * t;
        float2 bv = *(const float2*)(fc2_b + col);
        size_t r0 = tokBase + m0 + g;
        size_t r1 = r0 + 8;
        float2 h0 = *(const float2*)(g_h + r0 * 192 + col);
        float2 h1 = *(const float2*)(g_h + r1 * 192 + col);
        float2 o0 = make_float2(c2[nt][0] + bv.x + h0.x, c2[nt][1] + bv.y + h0.y);
        float2 o1 = make_float2(c2[nt][2] + bv.x + h1.x, c2[nt][3] + bv.y + h1.y);
        *(float2*)(out + r0 * 192 + col) = o0;
        *(float2*)(out + r1 * 192 + col) = o1;
    }
}

// ---------------- launch ----------------
extern "C" void kernel_launch(void* const* d_in, const int* in_sizes, int n_in,
                              void* d_out, int out_size) {
    (void)in_sizes; (void)n_in; (void)out_size;
    const float* x      = (const float*)d_in[0];
    const float* n1g    = (const float*)d_in[1];
    const float* n1b    = (const float*)d_in[2];
    const float* qkv_w  = (const float*)d_in[3];
    const float* qkv_b  = (const float*)d_in[4];
    const float* proj_w = (const float*)d_in[5];
    const float* proj_b = (const float*)d_in[6];
    const float* rpb    = (const float*)d_in[7];
    const float* n2g    = (const float*)d_in[8];
    const float* n2b    = (const float*)d_in[9];
    const float* fc1_w  = (const float*)d_in[10];
    const float* fc1_b  = (const float*)d_in[11];
    const float* fc2_w  = (const float*)d_in[12];
    const float* fc2_b  = (const float*)d_in[13];
    float* out = (float*)d_out;

    cudaFuncSetAttribute(attn_kernel, cudaFuncAttributeMaxDynamicSharedMemorySize,
                         ATTN_SMEM_BYTES);
    cudaFuncSetAttribute(mlp_kernel, cudaFuncAttributeMaxDynamicSharedMemorySize,
                         MLP_SMEM_BYTES);

    prep_kernel<<<432, 256>>>(qkv_w, proj_w, fc1_w, fc2_w);
    attn_kernel<<<4096, 384, ATTN_SMEM_BYTES>>>(x, n1g, n1b, qkv_b, proj_b, rpb);
    mlp_kernel<<<2048, 512, MLP_SMEM_BYTES>>>(n2g, n2b, fc1_b, fc2_b, out);
}

// round 11
// speedup vs baseline: 4.4373x; 1.4839x over previous
#include <cuda_runtime.h>
#include <cuda_bf16.h>
#include <cstdint>

// ---------------- problem constants ----------------
#define SHIFT_  4
#define SCALE_  0.1767766952966369f   // 32^-0.5
#define TOK     262144                // B*H*W
#define C_      192
#define QS      194                   // s_q fp32 stride

// bf16 tile strides (elements): row stride*2 bytes == 16 mod 128 -> conflict-free frags
#define AXS   200   // s_x / s_a bf16 stride
#define WKS   72    // weight tile stride for [n][64k] tiles
#define W1S   200   // fc1 weight tile stride for [n][192k] tiles
#define TSS   72    // GELU activation bf16 stride

// attn smem (floats): q(12416) k(12288) v(12288) rpb(1352) mu(64) rs(64) lab(64) row(64)
//                     xh bf16 64x200 (6400 fl)  w bf16 192x72 (6912 fl)
#define ATTN_Q    0
#define ATTN_K    12416
#define ATTN_V    24704
#define ATTN_RPB  36992
#define ATTN_MU   38344
#define ATTN_RS   38408
#define ATTN_LAB  38472
#define ATTN_ROW  38536
#define ATTN_XH   38600
#define ATTN_W    45000
#define ATTN_SMEM_BYTES (51912 * 4)    // 207648

// mlp smem (floats): mu(128) rs(128) a bf16 128x200 (12800 fl) b bf16 (6912 fl) t bf16 (4608 fl)
#define MLP_MU   0
#define MLP_RS   128
#define MLP_A    256
#define MLP_B    13056
#define MLP_T    19968
#define MLP_SMEM_BYTES (24576 * 4)     // 98304

// ---------------- device scratch ----------------
static __device__ float g_h[TOK * C_];
static __device__ __nv_bfloat16 g_qkvw[576 * 192];   // [o][k], bf16
static __device__ __nv_bfloat16 g_projw[192 * 192];  // [o][k]
static __device__ __nv_bfloat16 g_fc1w[768 * 192];   // [o][k]
static __device__ __nv_bfloat16 g_fc2w[192 * 768];   // [o][k]

// ---------------- helpers ----------------
__device__ __forceinline__ void mma16(float* c,
                                      uint32_t a0, uint32_t a1, uint32_t a2, uint32_t a3,
                                      uint32_t b0, uint32_t b1) {
    asm volatile(
        "mma.sync.aligned.m16n8k16.row.col.f32.bf16.bf16.f32 "
        "{%0,%1,%2,%3}, {%4,%5,%6,%7}, {%8,%9}, {%0,%1,%2,%3};"
        : "+f"(c[0]), "+f"(c[1]), "+f"(c[2]), "+f"(c[3])
        : "r"(a0), "r"(a1), "r"(a2), "r"(a3), "r"(b0), "r"(b1));
}
__device__ __forceinline__ uint32_t LD2(const __nv_bfloat16* p) {
    return *(const uint32_t*)p;
}
__device__ __forceinline__ uint32_t PK2(float a, float b) {
    __nv_bfloat162 h = __floats2bfloat162_rn(a, b);   // .x = a (low half = first col)
    return *(uint32_t*)&h;
}

// ---------------- prep: elementwise bf16 convert (layout preserved) ----------------
__global__ void prep_kernel(const float* __restrict__ qkv_w,
                            const float* __restrict__ proj_w,
                            const float* __restrict__ fc1_w,
                            const float* __restrict__ fc2_w) {
    int idx = blockIdx.x * blockDim.x + threadIdx.x;
    int stride = gridDim.x * blockDim.x;
    for (int i = idx; i < 576 * 192; i += stride) g_qkvw[i]  = __float2bfloat16(qkv_w[i]);
    for (int i = idx; i < 192 * 192; i += stride) g_projw[i] = __float2bfloat16(proj_w[i]);
    for (int i = idx; i < 768 * 192; i += stride) g_fc1w[i]  = __float2bfloat16(fc1_w[i]);
    for (int i = idx; i < 192 * 768; i += stride) g_fc2w[i]  = __float2bfloat16(fc2_w[i]);
}

// ---------------- fused window attention (bf16 mma GEMMs) ----------------
// One CTA per window. 384 threads = 12 warps: m-group = warp&3 (16 rows), n-group = warp>>2 (64 cols)
__global__ __launch_bounds__(384, 1)
void attn_kernel(const float* __restrict__ x,
                 const float* __restrict__ n1g, const float* __restrict__ n1b,
                 const float* __restrict__ qkv_b,
                 const float* __restrict__ proj_b,
                 const float* __restrict__ rpb) {
    extern __shared__ float sm[];
    float* s_q   = sm + ATTN_Q;
    float* s_k   = sm + ATTN_K;
    float* s_v   = sm + ATTN_V;
    float* s_rpb = sm + ATTN_RPB;
    float* s_mu  = sm + ATTN_MU;
    float* s_rs  = sm + ATTN_RS;
    int*   s_lab = (int*)(sm + ATTN_LAB);
    int*   s_row = (int*)(sm + ATTN_ROW);
    __nv_bfloat16* s_xh = (__nv_bfloat16*)(sm + ATTN_XH);   // [64][AXS]
    __nv_bfloat16* s_w  = (__nv_bfloat16*)(sm + ATTN_W);    // [192][WKS]

    const int tid  = threadIdx.x;
    const int w    = blockIdx.x;
    const int bimg = w >> 8;
    const int widx = w & 255;
    const int wh   = widx >> 4, ww = widx & 15;

    for (int i = tid; i < 1350; i += 384) s_rpb[i] = rpb[i];

    // LN1 stats + metadata
    if (tid < 64) {
        int r = tid >> 3, c2 = tid & 7;
        int hs = wh * 8 + r, wsc = ww * 8 + c2;
        int h0 = (hs + SHIFT_) & 127;
        int w0 = (wsc + SHIFT_) & 127;
        int row = bimg * 16384 + h0 * 128 + w0;
        s_row[tid] = row;
        int hreg = hs < 120 ? 0 : (hs < 124 ? 1 : 2);
        int wreg = wsc < 120 ? 0 : (wsc < 124 ? 1 : 2);
        s_lab[tid] = hreg * 3 + wreg;

        const float* xr = x + (size_t)row * 192;
        float s = 0.f, ss = 0.f;
        #pragma unroll 8
        for (int k4 = 0; k4 < 192; k4 += 4) {
            float4 v = *(const float4*)(xr + k4);
            s  += v.x + v.y + v.z + v.w;
            ss += v.x * v.x + v.y * v.y + v.z * v.z + v.w * v.w;
        }
        float mu = s * (1.f / 192.f);
        s_mu[tid] = mu;
        s_rs[tid] = rsqrtf(ss * (1.f / 192.f) - mu * mu + 1e-5f);
    }
    __syncthreads();

    // LN1 normalize -> s_xh bf16 (6144 pairs, 16 per thread)
    #pragma unroll
    for (int j = 0; j < 16; ++j) {
        int e2 = tid + j * 384;
        int row = e2 / 96, c = (e2 % 96) * 2;
        float mu = s_mu[row], rs = s_rs[row];
        float2 v  = *(const float2*)(x + (size_t)s_row[row] * 192 + c);
        float2 gv = *(const float2*)(n1g + c);
        float2 bv = *(const float2*)(n1b + c);
        *(uint32_t*)(s_xh + row * AXS + c) =
            PK2((v.x - mu) * rs * gv.x + bv.x, (v.y - mu) * rs * gv.y + bv.y);
    }

    const int lane = tid & 31, warp = tid >> 5;
    const int g = lane >> 2, t = lane & 3;
    const int m0  = (warp & 3) * 16;
    const int n0c = (warp >> 2) * 64;

    // -------- Phase A: qkv projection (3 passes) --------
    #pragma unroll 1
    for (int p = 0; p < 3; ++p) {
        float c1[8][4] = {};
        #pragma unroll 1
        for (int kb = 0; kb < 192; kb += 64) {
            __syncthreads();
            // stage [192 n][64 k] of qkv_w (bf16), 1536 float4, 4 per thread
            #pragma unroll
            for (int r = 0; r < 4; ++r) {
                int idx = r * 384 + tid;
                int row = idx >> 3, q4 = idx & 7;
                *(float4*)(s_w + row * WKS + q4 * 8) =
                    *(const float4*)(g_qkvw + (p * 192 + row) * 192 + kb + q4 * 8);
            }
            __syncthreads();
            #pragma unroll
            for (int ks = 0; ks < 4; ++ks) {
                int kg = kb + ks * 16, kl = ks * 16;
                uint32_t a0 = LD2(s_xh + (m0 + g)     * AXS + kg + 2 * t);
                uint32_t a1 = LD2(s_xh + (m0 + g + 8) * AXS + kg + 2 * t);
                uint32_t a2 = LD2(s_xh + (m0 + g)     * AXS + kg + 2 * t + 8);
                uint32_t a3 = LD2(s_xh + (m0 + g + 8) * AXS + kg + 2 * t + 8);
                #pragma unroll
                for (int nt = 0; nt < 8; ++nt) {
                    const __nv_bfloat16* br = s_w + (n0c + nt * 8 + g) * WKS + kl;
                    uint32_t b0 = LD2(br + 2 * t);
                    uint32_t b1 = LD2(br + 2 * t + 8);
                    mma16(c1[nt], a0, a1, a2, a3, b0, b1);
                }
            }
        }
        #pragma unroll
        for (int nt = 0; nt < 8; ++nt) {
            int col = n0c + nt * 8 + 2 * t;
            float2 bv = *(const float2*)(qkv_b + p * 192 + col);
            int r0 = m0 + g, r1 = m0 + g + 8;
            if (p == 0) {
                *(float2*)(s_q + r0 * QS + col) =
                    make_float2((c1[nt][0] + bv.x) * SCALE_, (c1[nt][1] + bv.y) * SCALE_);
                *(float2*)(s_q + r1 * QS + col) =
                    make_float2((c1[nt][2] + bv.x) * SCALE_, (c1[nt][3] + bv.y) * SCALE_);
            } else {
                float* dst = (p == 1) ? s_k : s_v;
                *(float2*)(dst + r0 * 192 + col) = make_float2(c1[nt][0] + bv.x, c1[nt][1] + bv.y);
                *(float2*)(dst + r1 * 192 + col) = make_float2(c1[nt][2] + bv.x, c1[nt][3] + bv.y);
            }
        }
    }
    __syncthreads();

    // -------- Phase B: attention (SIMT fp32, one thread per head x query) --------
    {
        const int head = tid / 64;
        const int n    = tid & 63;
        const int hb   = head * 32;
        float qv[32];
        #pragma unroll
        for (int d = 0; d < 32; ++d) qv[d] = s_q[n * QS + hb + d];

        float sc[64];
        const int i1 = n >> 3, j1 = n & 7;
        const int labn = s_lab[n];
        #pragma unroll
        for (int m = 0; m < 64; ++m) {
            const float* kr = s_k + m * 192 + hb;
            float s = 0.f;
            #pragma unroll
            for (int dq = 0; dq < 8; ++dq) {
                float4 k4 = *(const float4*)(kr + dq * 4);
                s += qv[dq * 4 + 0] * k4.x + qv[dq * 4 + 1] * k4.y
                   + qv[dq * 4 + 2] * k4.z + qv[dq * 4 + 3] * k4.w;
            }
            int i2 = m >> 3, j2 = m & 7;
            int ridx = (i1 - i2 + 7) * 15 + (j1 - j2 + 7);
            s += s_rpb[ridx * 6 + head];
            if (labn != s_lab[m]) s -= 100.f;
            sc[m] = s;
        }
        float mx = sc[0];
        #pragma unroll
        for (int m = 1; m < 64; ++m) mx = fmaxf(mx, sc[m]);
        float sum = 0.f;
        #pragma unroll
        for (int m = 0; m < 64; ++m) { sc[m] = expf(sc[m] - mx); sum += sc[m]; }
        float inv = 1.f / sum;

        float ov[32] = {};
        #pragma unroll
        for (int m = 0; m < 64; ++m) {
            float pm = sc[m];
            const float* vr = s_v + m * 192 + hb;
            #pragma unroll
            for (int dq = 0; dq < 8; ++dq) {
                float4 v4 = *(const float4*)(vr + dq * 4);
                ov[dq * 4 + 0] += pm * v4.x; ov[dq * 4 + 1] += pm * v4.y;
                ov[dq * 4 + 2] += pm * v4.z; ov[dq * 4 + 3] += pm * v4.w;
            }
        }
        #pragma unroll
        for (int d = 0; d < 32; d += 2)
            *(uint32_t*)(s_xh + n * AXS + hb + d) = PK2(ov[d] * inv, ov[d + 1] * inv);
    }

    // -------- Phase D: output projection + residual + scatter --------
    {
        float c1[8][4] = {};
        #pragma unroll 1
        for (int kb = 0; kb < 192; kb += 64) {
            __syncthreads();
            #pragma unroll
            for (int r = 0; r < 4; ++r) {
                int idx = r * 384 + tid;
                int row = idx >> 3, q4 = idx & 7;
                *(float4*)(s_w + row * WKS + q4 * 8) =
                    *(const float4*)(g_projw + row * 192 + kb + q4 * 8);
            }
            __syncthreads();
            #pragma unroll
            for (int ks = 0; ks < 4; ++ks) {
                int kg = kb + ks * 16, kl = ks * 16;
                uint32_t a0 = LD2(s_xh + (m0 + g)     * AXS + kg + 2 * t);
                uint32_t a1 = LD2(s_xh + (m0 + g + 8) * AXS + kg + 2 * t);
                uint32_t a2 = LD2(s_xh + (m0 + g)     * AXS + kg + 2 * t + 8);
                uint32_t a3 = LD2(s_xh + (m0 + g + 8) * AXS + kg + 2 * t + 8);
                #pragma unroll
                for (int nt = 0; nt < 8; ++nt) {
                    const __nv_bfloat16* br = s_w + (n0c + nt * 8 + g) * WKS + kl;
                    uint32_t b0 = LD2(br + 2 * t);
                    uint32_t b1 = LD2(br + 2 * t + 8);
                    mma16(c1[nt], a0, a1, a2, a3, b0, b1);
                }
            }
        }
        int r0 = m0 + g, r1 = m0 + g + 8;
        size_t row0 = (size_t)s_row[r0], row1 = (size_t)s_row[r1];
        #pragma unroll
        for (int nt = 0; nt < 8; ++nt) {
            int col = n0c + nt * 8 + 2 * t;
            float2 pb = *(const float2*)(proj_b + col);
            float2 x0 = *(const float2*)(x + row0 * 192 + col);
            float2 x1 = *(const float2*)(x + row1 * 192 + col);
            *(float2*)(g_h + row0 * 192 + col) =
                make_float2(c1[nt][0] + pb.x + x0.x, c1[nt][1] + pb.y + x0.y);
            *(float2*)(g_h + row1 * 192 + col) =
                make_float2(c1[nt][2] + pb.x + x1.x, c1[nt][3] + pb.y + x1.y);
        }
    }
}

// ---------------- MLP via bf16 mma ----------------
// One CTA per 128 tokens (grid 2048). 512 threads = 16 warps, 8m x 2n.
__global__ __launch_bounds__(512, 1)
void mlp_kernel(const float* __restrict__ n2g, const float* __restrict__ n2b,
                const float* __restrict__ fc1_b, const float* __restrict__ fc2_b,
                float* __restrict__ out) {
    extern __shared__ float sm[];
    float* s_mu = sm + MLP_MU;
    float* s_rs = sm + MLP_RS;
    __nv_bfloat16* s_a = (__nv_bfloat16*)(sm + MLP_A);   // [128][AXS]
    __nv_bfloat16* s_b = (__nv_bfloat16*)(sm + MLP_B);   // W1 [64][W1S] / W2 [192][WKS]
    __nv_bfloat16* s_t = (__nv_bfloat16*)(sm + MLP_T);   // [128][TSS]

    const int tid  = threadIdx.x;
    const int lane = tid & 31, warp = tid >> 5;
    const int g = lane >> 2, t = lane & 3;
    const int wm = warp >> 1, wn = warp & 1;
    const int m0 = wm * 16;
    const size_t tokBase = (size_t)blockIdx.x * 128;

    // LN2 stats
    if (tid < 128) {
        const float* hr = g_h + (tokBase + tid) * 192;
        float s = 0.f, ss = 0.f;
        #pragma unroll 8
        for (int k4 = 0; k4 < 192; k4 += 4) {
            float4 v = *(const float4*)(hr + k4);
            s  += v.x + v.y + v.z + v.w;
            ss += v.x * v.x + v.y * v.y + v.z * v.z + v.w * v.w;
        }
        float mu = s * (1.f / 192.f);
        s_mu[tid] = mu;
        s_rs[tid] = rsqrtf(ss * (1.f / 192.f) - mu * mu + 1e-5f);
    }
    __syncthreads();

    // LN2 normalize -> s_a bf16 (12288 pairs, 24 per thread)
    #pragma unroll
    for (int j = 0; j < 24; ++j) {
        int e2 = tid + j * 512;
        int row = e2 / 96, c = (e2 % 96) * 2;
        float mu = s_mu[row], rs = s_rs[row];
        float2 v  = *(const float2*)(g_h + (tokBase + row) * 192 + c);
        float2 gv = *(const float2*)(n2g + c);
        float2 bv = *(const float2*)(n2b + c);
        *(uint32_t*)(s_a + row * AXS + c) =
            PK2((v.x - mu) * rs * gv.x + bv.x, (v.y - mu) * rs * gv.y + bv.y);
    }

    float c2[12][4] = {};

    for (int oc = 0; oc < 768; oc += 64) {
        __syncthreads();

        // stage W1 chunk: [64 n][192 k], 1536 float4, 3 per thread
        #pragma unroll
        for (int r = 0; r < 3; ++r) {
            int idx = r * 512 + tid;
            int row = idx / 24, q4 = idx % 24;
            *(float4*)(s_b + row * W1S + q4 * 8) =
                *(const float4*)(g_fc1w + (oc + row) * 192 + q4 * 8);
        }
        __syncthreads();

        // fc1: C1[128x64] = A[128x192] @ W1^T
        float c1[4][4] = {};
        #pragma unroll
        for (int ks = 0; ks < 12; ++ks) {
            int k0 = ks * 16;
            uint32_t a0 = LD2(s_a + (m0 + g)     * AXS + k0 + 2 * t);
            uint32_t a1 = LD2(s_a + (m0 + g + 8) * AXS + k0 + 2 * t);
            uint32_t a2 = LD2(s_a + (m0 + g)     * AXS + k0 + 2 * t + 8);
            uint32_t a3 = LD2(s_a + (m0 + g + 8) * AXS + k0 + 2 * t + 8);
            #pragma unroll
            for (int nt = 0; nt < 4; ++nt) {
                const __nv_bfloat16* br = s_b + (wn * 32 + nt * 8 + g) * W1S + k0;
                uint32_t b0 = LD2(br + 2 * t);
                uint32_t b1 = LD2(br + 2 * t + 8);
                mma16(c1[nt], a0, a1, a2, a3, b0, b1);
            }
        }

        // GELU + bias -> s_t bf16
        #pragma unroll
        for (int nt = 0; nt < 4; ++nt) {
            int ncol = wn * 32 + nt * 8 + 2 * t;
            float b0f = fc1_b[oc + ncol], b1f = fc1_b[oc + ncol + 1];
            float v0 = c1[nt][0] + b0f, v1 = c1[nt][1] + b1f;
            float v2 = c1[nt][2] + b0f, v3 = c1[nt][3] + b1f;
            v0 = 0.5f * v0 * (1.f + erff(v0 * 0.70710678118654752f));
            v1 = 0.5f * v1 * (1.f + erff(v1 * 0.70710678118654752f));
            v2 = 0.5f * v2 * (1.f + erff(v2 * 0.70710678118654752f));
            v3 = 0.5f * v3 * (1.f + erff(v3 * 0.70710678118654752f));
            *(uint32_t*)(s_t + (m0 + g)     * TSS + ncol) = PK2(v0, v1);
            *(uint32_t*)(s_t + (m0 + g + 8) * TSS + ncol) = PK2(v2, v3);
        }
        __syncthreads();

        // stage W2 chunk: [192 n][64 k], 1536 float4, 3 per thread
        #pragma unroll
        for (int r = 0; r < 3; ++r) {
            int idx = r * 512 + tid;
            int row = idx >> 3, q4 = idx & 7;
            *(float4*)(s_b + row * WKS + q4 * 8) =
                *(const float4*)(g_fc2w + row * 768 + oc + q4 * 8);
        }
        __syncthreads();

        // fc2 partial: C2[128x192] += T[128x64] @ W2^T
        #pragma unroll
        for (int ks = 0; ks < 4; ++ks) {
            int k0 = ks * 16;
            uint32_t a0 = LD2(s_t + (m0 + g)     * TSS + k0 + 2 * t);
            uint32_t a1 = LD2(s_t + (m0 + g + 8) * TSS + k0 + 2 * t);
            uint32_t a2 = LD2(s_t + (m0 + g)     * TSS + k0 + 2 * t + 8);
            uint32_t a3 = LD2(s_t + (m0 + g + 8) * TSS + k0 + 2 * t + 8);
            #pragma unroll
            for (int nt = 0; nt < 12; ++nt) {
                const __nv_bfloat16* br = s_b + (wn * 96 + nt * 8 + g) * WKS + k0;
                uint32_t b0 = LD2(br + 2 * t);
                uint32_t b1 = LD2(br + 2 * t + 8);
                mma16(c2[nt], a0, a1, a2, a3, b0, b1);
            }
        }
    }

    // epilogue: out = h + fc2 + bias
    #pragma unroll
    for (int nt = 0; nt < 12; ++nt) {
        int col = wn * 96 + nt * 8 + 2 * t;
        float2 bv = *(const float2*)(fc2_b + col);
        size_t r0 = tokBase + m0 + g;
        size_t r1 = r0 + 8;
        float2 h0 = *(const float2*)(g_h + r0 * 192 + col);
        float2 h1 = *(const float2*)(g_h + r1 * 192 + col);
        *(float2*)(out + r0 * 192 + col) =
            make_float2(c2[nt][0] + bv.x + h0.x, c2[nt][1] + bv.y + h0.y);
        *(float2*)(out + r1 * 192 + col) =
            make_float2(c2[nt][2] + bv.x + h1.x, c2[nt][3] + bv.y + h1.y);
    }
}

// ---------------- launch ----------------
extern "C" void kernel_launch(void* const* d_in, const int* in_sizes, int n_in,
                              void* d_out, int out_size) {
    (void)in_sizes; (void)n_in; (void)out_size;
    const float* x      = (const float*)d_in[0];
    const float* n1g    = (const float*)d_in[1];
    const float* n1b    = (const float*)d_in[2];
    const float* qkv_w  = (const float*)d_in[3];
    const float* qkv_b  = (const float*)d_in[4];
    const float* proj_w = (const float*)d_in[5];
    const float* proj_b = (const float*)d_in[6];
    const float* rpb    = (const float*)d_in[7];
    const float* n2g    = (const float*)d_in[8];
    const float* n2b    = (const float*)d_in[9];
    const float* fc1_w  = (const float*)d_in[10];
    const float* fc1_b  = (const float*)d_in[11];
    const float* fc2_w  = (const float*)d_in[12];
    const float* fc2_b  = (const float*)d_in[13];
    float* out = (float*)d_out;

    cudaFuncSetAttribute(attn_kernel, cudaFuncAttributeMaxDynamicSharedMemorySize,
                         ATTN_SMEM_BYTES);
    cudaFuncSetAttribute(mlp_kernel, cudaFuncAttributeMaxDynamicSharedMemorySize,
                         MLP_SMEM_BYTES);

    prep_kernel<<<432, 256>>>(qkv_w, proj_w, fc1_w, fc2_w);
    attn_kernel<<<4096, 384, ATTN_SMEM_BYTES>>>(x, n1g, n1b, qkv_b, proj_b, rpb);
    mlp_kernel<<<2048, 512, MLP_SMEM_BYTES>>>(n2g, n2b, fc1_b, fc2_b, out);
}

// round 13
// speedup vs baseline: 4.6106x; 1.0391x over previous
#include <cuda_runtime.h>
#include <cuda_bf16.h>
#include <cstdint>

// ---------------- problem constants ----------------
#define SHIFT_  4
#define SCALE_  0.1767766952966369f   // 32^-0.5
#define TOK     262144                // B*H*W
#define C_      192
#define QS      194                   // s_q fp32 stride

// bf16 tile strides (elements): row stride*2 bytes == 16 mod 128 -> conflict-free frags/LDSM
#define AXS   200   // s_x / s_a bf16 stride
#define WKS   72    // weight tile stride for [n][64k] tiles
#define W1S   200   // fc1 weight tile stride for [n][192k] tiles
#define TSS   72    // GELU activation bf16 stride

// attn smem (floats)
#define ATTN_Q    0
#define ATTN_K    12416
#define ATTN_V    24704
#define ATTN_RPB  36992
#define ATTN_MU   38344
#define ATTN_RS   38408
#define ATTN_LAB  38472
#define ATTN_ROW  38536
#define ATTN_XH   38600
#define ATTN_W    45000
#define ATTN_SMEM_BYTES (51912 * 4)    // 207648

// mlp smem (floats)
#define MLP_MU   0
#define MLP_RS   128
#define MLP_A    256
#define MLP_B    13056
#define MLP_T    19968
#define MLP_SMEM_BYTES (24576 * 4)     // 98304

// ---------------- device scratch ----------------
static __device__ float g_h[TOK * C_];
static __device__ __nv_bfloat16 g_qkvw[576 * 192];   // [o][k], bf16
static __device__ __nv_bfloat16 g_projw[192 * 192];  // [o][k]
static __device__ __nv_bfloat16 g_fc1w[768 * 192];   // [o][k]
static __device__ __nv_bfloat16 g_fc2w[192 * 768];   // [o][k]

// ---------------- helpers ----------------
__device__ __forceinline__ void mma16(float* c,
                                      uint32_t a0, uint32_t a1, uint32_t a2, uint32_t a3,
                                      uint32_t b0, uint32_t b1) {
    asm volatile(
        "mma.sync.aligned.m16n8k16.row.col.f32.bf16.bf16.f32 "
        "{%0,%1,%2,%3}, {%4,%5,%6,%7}, {%8,%9}, {%0,%1,%2,%3};"
        : "+f"(c[0]), "+f"(c[1]), "+f"(c[2]), "+f"(c[3])
        : "r"(a0), "r"(a1), "r"(a2), "r"(a3), "r"(b0), "r"(b1));
}
// ldmatrix x4 (non-transposed): 4 8x8 b16 matrices; lane groups of 8 supply row addrs
__device__ __forceinline__ void ldm4(uint32_t& r0, uint32_t& r1, uint32_t& r2, uint32_t& r3,
                                     uint32_t addr) {
    asm volatile("ldmatrix.sync.aligned.m8n8.x4.shared.b16 {%0,%1,%2,%3}, [%4];"
                 : "=r"(r0), "=r"(r1), "=r"(r2), "=r"(r3) : "r"(addr));
}
__device__ __forceinline__ uint32_t PK2(float a, float b) {
    __nv_bfloat162 h = __floats2bfloat162_rn(a, b);
    return *(uint32_t*)&h;
}
__device__ __forceinline__ uint32_t SADDR(const void* p) {
    return (uint32_t)__cvta_generic_to_shared(p);
}
// exact-GELU via Abramowitz-Stegun 7.1.26 erf approx (|abs err| <= 1.5e-7)
__device__ __forceinline__ float gelu_f(float x) {
    float z  = x * 0.70710678118654752f;
    float az = fabsf(z);
    float t  = __fdividef(1.f, fmaf(0.3275911f, az, 1.f));
    float p  = fmaf(1.061405429f, t, -1.453152027f);
    p = fmaf(p, t, 1.421413741f);
    p = fmaf(p, t, -0.284496736f);
    p = fmaf(p, t, 0.254829592f);
    p = p * t;
    float erfv = copysignf(1.f - p * __expf(-az * az), z);
    return 0.5f * x * (1.f + erfv);
}

// ---------------- prep: elementwise bf16 convert ----------------
__global__ void prep_kernel(const float* __restrict__ qkv_w,
                            const float* __restrict__ proj_w,
                            const float* __restrict__ fc1_w,
                            const float* __restrict__ fc2_w) {
    int idx = blockIdx.x * blockDim.x + threadIdx.x;
    int stride = gridDim.x * blockDim.x;
    for (int i = idx; i < 576 * 192; i += stride) g_qkvw[i]  = __float2bfloat16(qkv_w[i]);
    for (int i = idx; i < 192 * 192; i += stride) g_projw[i] = __float2bfloat16(proj_w[i]);
    for (int i = idx; i < 768 * 192; i += stride) g_fc1w[i]  = __float2bfloat16(fc1_w[i]);
    for (int i = idx; i < 192 * 768; i += stride) g_fc2w[i]  = __float2bfloat16(fc2_w[i]);
}

// ---------------- fused window attention ----------------
__global__ __launch_bounds__(384, 1)
void attn_kernel(const float* __restrict__ x,
                 const float* __restrict__ n1g, const float* __restrict__ n1b,
                 const float* __restrict__ qkv_b,
                 const float* __restrict__ proj_b,
                 const float* __restrict__ rpb) {
    extern __shared__ float sm[];
    float* s_q   = sm + ATTN_Q;
    float* s_k   = sm + ATTN_K;
    float* s_v   = sm + ATTN_V;
    float* s_rpb = sm + ATTN_RPB;
    float* s_mu  = sm + ATTN_MU;
    float* s_rs  = sm + ATTN_RS;
    int*   s_lab = (int*)(sm + ATTN_LAB);
    int*   s_row = (int*)(sm + ATTN_ROW);
    __nv_bfloat16* s_xh = (__nv_bfloat16*)(sm + ATTN_XH);   // [64][AXS]
    __nv_bfloat16* s_w  = (__nv_bfloat16*)(sm + ATTN_W);    // [192][WKS]

    const int tid  = threadIdx.x;
    const int w    = blockIdx.x;
    const int bimg = w >> 8;
    const int widx = w & 255;
    const int wh   = widx >> 4, ww = widx & 15;

    for (int i = tid; i < 1350; i += 384) s_rpb[i] = rpb[i];

    if (tid < 64) {
        int r = tid >> 3, c2 = tid & 7;
        int hs = wh * 8 + r, wsc = ww * 8 + c2;
        int h0 = (hs + SHIFT_) & 127;
        int w0 = (wsc + SHIFT_) & 127;
        int row = bimg * 16384 + h0 * 128 + w0;
        s_row[tid] = row;
        int hreg = hs < 120 ? 0 : (hs < 124 ? 1 : 2);
        int wreg = wsc < 120 ? 0 : (wsc < 124 ? 1 : 2);
        s_lab[tid] = hreg * 3 + wreg;

        const float* xr = x + (size_t)row * 192;
        float s = 0.f, ss = 0.f;
        #pragma unroll 8
        for (int k4 = 0; k4 < 192; k4 += 4) {
            float4 v = *(const float4*)(xr + k4);
            s  += v.x + v.y + v.z + v.w;
            ss += v.x * v.x + v.y * v.y + v.z * v.z + v.w * v.w;
        }
        float mu = s * (1.f / 192.f);
        s_mu[tid] = mu;
        s_rs[tid] = rsqrtf(ss * (1.f / 192.f) - mu * mu + 1e-5f);
    }
    __syncthreads();

    // LN1 normalize -> s_xh bf16
    #pragma unroll
    for (int j = 0; j < 16; ++j) {
        int e2 = tid + j * 384;
        int row = e2 / 96, c = (e2 % 96) * 2;
        float mu = s_mu[row], rs = s_rs[row];
        float2 v  = *(const float2*)(x + (size_t)s_row[row] * 192 + c);
        float2 gv = *(const float2*)(n1g + c);
        float2 bv = *(const float2*)(n1b + c);
        *(uint32_t*)(s_xh + row * AXS + c) =
            PK2((v.x - mu) * rs * gv.x + bv.x, (v.y - mu) * rs * gv.y + bv.y);
    }

    const int lane = tid & 31, warp = tid >> 5;
    const int g = lane >> 2, t = lane & 3;
    const int m0  = (warp & 3) * 16;
    const int n0c = (warp >> 2) * 64;

    // ldmatrix per-lane address bases (elements -> *2 bytes)
    // A-frag: lanes 0-7: rows m0+0..7 @k; 8-15: m0+8..15 @k; 16-23: m0+0..7 @k+8; 24-31: m0+8..15 @k+8
    const uint32_t aBase = SADDR(s_xh) +
        (((m0 + (lane & 7) + ((lane >> 3) & 1) * 8) * AXS) + ((lane >> 4) * 8)) * 2;
    // B-frag pair: lanes 0-7: n rows base..+7 @k; 8-15: same rows @k+8; 16-23: rows +8 @k; 24-31: rows +8 @k+8
    const int bRowOff = (lane & 7) + ((lane >> 4) & 1) * 8;
    const int bKOff   = ((lane >> 3) & 1) * 8;

    // -------- Phase A: qkv projection (3 passes) --------
    #pragma unroll 1
    for (int p = 0; p < 3; ++p) {
        float c1[8][4] = {};
        #pragma unroll 1
        for (int kb = 0; kb < 192; kb += 64) {
            __syncthreads();
            #pragma unroll
            for (int r = 0; r < 4; ++r) {
                int idx = r * 384 + tid;
                int row = idx >> 3, q4 = idx & 7;
                *(float4*)(s_w + row * WKS + q4 * 8) =
                    *(const float4*)(g_qkvw + (p * 192 + row) * 192 + kb + q4 * 8);
            }
            __syncthreads();
            #pragma unroll
            for (int ks = 0; ks < 4; ++ks) {
                int kg = kb + ks * 16, kl = ks * 16;
                uint32_t a0, a1, a2, a3;
                ldm4(a0, a1, a2, a3, aBase + kg * 2);
                #pragma unroll
                for (int np = 0; np < 4; ++np) {
                    uint32_t b0, b1, b2, b3;
                    uint32_t bAddr = SADDR(s_w) +
                        (((n0c + np * 16 + bRowOff) * WKS) + bKOff + kl) * 2;
                    ldm4(b0, b1, b2, b3, bAddr);
                    mma16(c1[np * 2],     a0, a1, a2, a3, b0, b1);
                    mma16(c1[np * 2 + 1], a0, a1, a2, a3, b2, b3);
                }
            }
        }
        #pragma unroll
        for (int nt = 0; nt < 8; ++nt) {
            int col = n0c + nt * 8 + 2 * t;
            float2 bv = *(const float2*)(qkv_b + p * 192 + col);
            int r0 = m0 + g, r1 = m0 + g + 8;
            if (p == 0) {
                *(float2*)(s_q + r0 * QS + col) =
                    make_float2((c1[nt][0] + bv.x) * SCALE_, (c1[nt][1] + bv.y) * SCALE_);
                *(float2*)(s_q + r1 * QS + col) =
                    make_float2((c1[nt][2] + bv.x) * SCALE_, (c1[nt][3] + bv.y) * SCALE_);
            } else {
                float* dst = (p == 1) ? s_k : s_v;
                *(float2*)(dst + r0 * 192 + col) = make_float2(c1[nt][0] + bv.x, c1[nt][1] + bv.y);
                *(float2*)(dst + r1 * 192 + col) = make_float2(c1[nt][2] + bv.x, c1[nt][3] + bv.y);
            }
        }
    }
    __syncthreads();

    // -------- Phase B: attention (SIMT fp32) --------
    {
        const int head = tid / 64;
        const int n    = tid & 63;
        const int hb   = head * 32;
        float qv[32];
        #pragma unroll
        for (int d = 0; d < 32; ++d) qv[d] = s_q[n * QS + hb + d];

        float sc[64];
        const int i1 = n >> 3, j1 = n & 7;
        const int labn = s_lab[n];
        #pragma unroll
        for (int m = 0; m < 64; ++m) {
            const float* kr = s_k + m * 192 + hb;
            float s = 0.f;
            #pragma unroll
            for (int dq = 0; dq < 8; ++dq) {
                float4 k4 = *(const float4*)(kr + dq * 4);
                s += qv[dq * 4 + 0] * k4.x + qv[dq * 4 + 1] * k4.y
                   + qv[dq * 4 + 2] * k4.z + qv[dq * 4 + 3] * k4.w;
            }
            int i2 = m >> 3, j2 = m & 7;
            int ridx = (i1 - i2 + 7) * 15 + (j1 - j2 + 7);
            s += s_rpb[ridx * 6 + head];
            if (labn != s_lab[m]) s -= 100.f;
            sc[m] = s;
        }
        float mx = sc[0];
        #pragma unroll
        for (int m = 1; m < 64; ++m) mx = fmaxf(mx, sc[m]);
        float sum = 0.f;
        #pragma unroll
        for (int m = 0; m < 64; ++m) { sc[m] = __expf(sc[m] - mx); sum += sc[m]; }
        float inv = 1.f / sum;

        float ov[32] = {};
        #pragma unroll
        for (int m = 0; m < 64; ++m) {
            float pm = sc[m];
            const float* vr = s_v + m * 192 + hb;
            #pragma unroll
            for (int dq = 0; dq < 8; ++dq) {
                float4 v4 = *(const float4*)(vr + dq * 4);
                ov[dq * 4 + 0] += pm * v4.x; ov[dq * 4 + 1] += pm * v4.y;
                ov[dq * 4 + 2] += pm * v4.z; ov[dq * 4 + 3] += pm * v4.w;
            }
        }
        #pragma unroll
        for (int d = 0; d < 32; d += 2)
            *(uint32_t*)(s_xh + n * AXS + hb + d) = PK2(ov[d] * inv, ov[d + 1] * inv);
    }

    // -------- Phase D: output projection + residual + scatter --------
    {
        float c1[8][4] = {};
        #pragma unroll 1
        for (int kb = 0; kb < 192; kb += 64) {
            __syncthreads();
            #pragma unroll
            for (int r = 0; r < 4; ++r) {
                int idx = r * 384 + tid;
                int row = idx >> 3, q4 = idx & 7;
                *(float4*)(s_w + row * WKS + q4 * 8) =
                    *(const float4*)(g_projw + row * 192 + kb + q4 * 8);
            }
            __syncthreads();
            #pragma unroll
            for (int ks = 0; ks < 4; ++ks) {
                int kg = kb + ks * 16, kl = ks * 16;
                uint32_t a0, a1, a2, a3;
                ldm4(a0, a1, a2, a3, aBase + kg * 2);
                #pragma unroll
                for (int np = 0; np < 4; ++np) {
                    uint32_t b0, b1, b2, b3;
                    uint32_t bAddr = SADDR(s_w) +
                        (((n0c + np * 16 + bRowOff) * WKS) + bKOff + kl) * 2;
                    ldm4(b0, b1, b2, b3, bAddr);
                    mma16(c1[np * 2],     a0, a1, a2, a3, b0, b1);
                    mma16(c1[np * 2 + 1], a0, a1, a2, a3, b2, b3);
                }
            }
        }
        int r0 = m0 + g, r1 = m0 + g + 8;
        size_t row0 = (size_t)s_row[r0], row1 = (size_t)s_row[r1];
        #pragma unroll
        for (int nt = 0; nt < 8; ++nt) {
            int col = n0c + nt * 8 + 2 * t;
            float2 pb = *(const float2*)(proj_b + col);
            float2 x0 = *(const float2*)(x + row0 * 192 + col);
            float2 x1 = *(const float2*)(x + row1 * 192 + col);
            *(float2*)(g_h + row0 * 192 + col) =
                make_float2(c1[nt][0] + pb.x + x0.x, c1[nt][1] + pb.y + x0.y);
            *(float2*)(g_h + row1 * 192 + col) =
                make_float2(c1[nt][2] + pb.x + x1.x, c1[nt][3] + pb.y + x1.y);
        }
    }
}

// ---------------- MLP via bf16 mma + ldmatrix ----------------
__global__ __launch_bounds__(512, 1)
void mlp_kernel(const float* __restrict__ n2g, const float* __restrict__ n2b,
                const float* __restrict__ fc1_b, const float* __restrict__ fc2_b,
                float* __restrict__ out) {
    extern __shared__ float sm[];
    float* s_mu = sm + MLP_MU;
    float* s_rs = sm + MLP_RS;
    __nv_bfloat16* s_a = (__nv_bfloat16*)(sm + MLP_A);   // [128][AXS]
    __nv_bfloat16* s_b = (__nv_bfloat16*)(sm + MLP_B);   // W1 [64][W1S] / W2 [192][WKS]
    __nv_bfloat16* s_t = (__nv_bfloat16*)(sm + MLP_T);   // [128][TSS]

    const int tid  = threadIdx.x;
    const int lane = tid & 31, warp = tid >> 5;
    const int g = lane >> 2, t = lane & 3;
    const int wm = warp >> 1, wn = warp & 1;
    const int m0 = wm * 16;
    const size_t tokBase = (size_t)blockIdx.x * 128;

    if (tid < 128) {
        const float* hr = g_h + (tokBase + tid) * 192;
        float s = 0.f, ss = 0.f;
        #pragma unroll 8
        for (int k4 = 0; k4 < 192; k4 += 4) {
            float4 v = *(const float4*)(hr + k4);
            s  += v.x + v.y + v.z + v.w;
            ss += v.x * v.x + v.y * v.y + v.z * v.z + v.w * v.w;
        }
        float mu = s * (1.f / 192.f);
        s_mu[tid] = mu;
        s_rs[tid] = rsqrtf(ss * (1.f / 192.f) - mu * mu + 1e-5f);
    }
    __syncthreads();

    #pragma unroll
    for (int j = 0; j < 24; ++j) {
        int e2 = tid + j * 512;
        int row = e2 / 96, c = (e2 % 96) * 2;
        float mu = s_mu[row], rs = s_rs[row];
        float2 v  = *(const float2*)(g_h + (tokBase + row) * 192 + c);
        float2 gv = *(const float2*)(n2g + c);
        float2 bv = *(const float2*)(n2b + c);
        *(uint32_t*)(s_a + row * AXS + c) =
            PK2((v.x - mu) * rs * gv.x + bv.x, (v.y - mu) * rs * gv.y + bv.y);
    }

    // ldmatrix lane-address components
    const int aRowOff = (lane & 7) + ((lane >> 3) & 1) * 8;   // A frag row-in-tile
    const int aKOff   = (lane >> 4) * 8;                      // A frag k half
    const uint32_t aBaseA = SADDR(s_a) + ((m0 + aRowOff) * AXS + aKOff) * 2;
    const uint32_t aBaseT = SADDR(s_t) + ((m0 + aRowOff) * TSS + aKOff) * 2;
    const int bRowOff = (lane & 7) + ((lane >> 4) & 1) * 8;
    const int bKOff   = ((lane >> 3) & 1) * 8;

    float c2[12][4] = {};

    for (int oc = 0; oc < 768; oc += 64) {
        __syncthreads();

        // stage W1 chunk: [64 n][192 k]
        #pragma unroll
        for (int r = 0; r < 3; ++r) {
            int idx = r * 512 + tid;
            int row = idx / 24, q4 = idx % 24;
            *(float4*)(s_b + row * W1S + q4 * 8) =
                *(const float4*)(g_fc1w + (oc + row) * 192 + q4 * 8);
        }
        __syncthreads();

        // fc1: C1[128x64] = A[128x192] @ W1^T
        float c1[4][4] = {};
        #pragma unroll
        for (int ks = 0; ks < 12; ++ks) {
            int k0 = ks * 16;
            uint32_t a0, a1, a2, a3;
            ldm4(a0, a1, a2, a3, aBaseA + k0 * 2);
            #pragma unroll
            for (int np = 0; np < 2; ++np) {
                uint32_t b0, b1, b2, b3;
                uint32_t bAddr = SADDR(s_b) +
                    ((wn * 32 + np * 16 + bRowOff) * W1S + bKOff + k0) * 2;
                ldm4(b0, b1, b2, b3, bAddr);
                mma16(c1[np * 2],     a0, a1, a2, a3, b0, b1);
                mma16(c1[np * 2 + 1], a0, a1, a2, a3, b2, b3);
            }
        }

        // GELU + bias -> s_t bf16
        #pragma unroll
        for (int nt = 0; nt < 4; ++nt) {
            int ncol = wn * 32 + nt * 8 + 2 * t;
            float b0f = fc1_b[oc + ncol], b1f = fc1_b[oc + ncol + 1];
            float v0 = gelu_f(c1[nt][0] + b0f), v1 = gelu_f(c1[nt][1] + b1f);
            float v2 = gelu_f(c1[nt][2] + b0f), v3 = gelu_f(c1[nt][3] + b1f);
            *(uint32_t*)(s_t + (m0 + g)     * TSS + ncol) = PK2(v0, v1);
            *(uint32_t*)(s_t + (m0 + g + 8) * TSS + ncol) = PK2(v2, v3);
        }
        __syncthreads();

        // stage W2 chunk: [192 n][64 k]
        #pragma unroll
        for (int r = 0; r < 3; ++r) {
            int idx = r * 512 + tid;
            int row = idx >> 3, q4 = idx & 7;
            *(float4*)(s_b + row * WKS + q4 * 8) =
                *(const float4*)(g_fc2w + row * 768 + oc + q4 * 8);
        }
        __syncthreads();

        // fc2 partial: C2[128x192] += T[128x64] @ W2^T
        #pragma unroll
        for (int ks = 0; ks < 4; ++ks) {
            int k0 = ks * 16;
            uint32_t a0, a1, a2, a3;
            ldm4(a0, a1, a2, a3, aBaseT + k0 * 2);
            #pragma unroll
            for (int np = 0; np < 6; ++np) {
                uint32_t b0, b1, b2, b3;
                uint32_t bAddr = SADDR(s_b) +
                    ((wn * 96 + np * 16 + bRowOff) * WKS + bKOff + k0) * 2;
                ldm4(b0, b1, b2, b3, bAddr);
                mma16(c2[np * 2],     a0, a1, a2, a3, b0, b1);
                mma16(c2[np * 2 + 1], a0, a1, a2, a3, b2, b3);
            }
        }
    }

    // epilogue: out = h + fc2 + bias
    #pragma unroll
    for (int nt = 0; nt < 12; ++nt) {
        int col = wn * 96 + nt * 8 + 2 * t;
        float2 bv = *(const float2*)(fc2_b + col);
        size_t r0 = tokBase + m0 + g;
        size_t r1 = r0 + 8;
        float2 h0 = *(const float2*)(g_h + r0 * 192 + col);
        float2 h1 = *(const float2*)(g_h + r1 * 192 + col);
        *(float2*)(out + r0 * 192 + col) =
            make_float2(c2[nt][0] + bv.x + h0.x, c2[nt][1] + bv.y + h0.y);
        *(float2*)(out + r1 * 192 + col) =
            make_float2(c2[nt][2] + bv.x + h1.x, c2[nt][3] + bv.y + h1.y);
    }
}

// ---------------- launch ----------------
extern "C" void kernel_launch(void* const* d_in, const int* in_sizes, int n_in,
                              void* d_out, int out_size) {
    (void)in_sizes; (void)n_in; (void)out_size;
    const float* x      = (const float*)d_in[0];
    const float* n1g    = (const float*)d_in[1];
    const float* n1b    = (const float*)d_in[2];
    const float* qkv_w  = (const float*)d_in[3];
    const float* qkv_b  = (const float*)d_in[4];
    const float* proj_w = (const float*)d_in[5];
    const float* proj_b = (const float*)d_in[6];
    const float* rpb    = (const float*)d_in[7];
    const float* n2g    = (const float*)d_in[8];
    const float* n2b    = (const float*)d_in[9];
    const float* fc1_w  = (const float*)d_in[10];
    const float* fc1_b  = (const float*)d_in[11];
    const float* fc2_w  = (const float*)d_in[12];
    const float* fc2_b  = (const float*)d_in[13];
    float* out = (float*)d_out;

    cudaFuncSetAttribute(attn_kernel, cudaFuncAttributeMaxDynamicSharedMemorySize,
                         ATTN_SMEM_BYTES);
    cudaFuncSetAttribute(mlp_kernel, cudaFuncAttributeMaxDynamicSharedMemorySize,
                         MLP_SMEM_BYTES);

    prep_kernel<<<432, 256>>>(qkv_w, proj_w, fc1_w, fc2_w);
    attn_kernel<<<4096, 384, ATTN_SMEM_BYTES>>>(x, n1g, n1b, qkv_b, proj_b, rpb);
    mlp_kernel<<<2048, 512, MLP_SMEM_BYTES>>>(n2g, n2b, fc1_b, fc2_b, out);
}